// round 1
// baseline (speedup 1.0000x reference)
#include <cuda_runtime.h>
#include <math.h>

// ---- problem constants ----
constexpr int B   = 256;
constexpr int N   = 4096;
constexpr int M   = 64;
constexpr int C   = 512;
constexpr int H   = 4;
constexpr int INP = 64;
constexpr int OUTD= 64;
constexpr int XPART = INP + H*M;      // 320
constexpr int KL    = XPART + C;      // 832
constexpr int NADDR = 2*H*(M+6);      // 560
constexpr int NEA   = H*2*M;          // 512
constexpr int BN_   = B*N;            // 1048576
constexpr float EPS = 1e-8f;

// ---- scratch (device globals: allocation-free) ----
__device__ float g_xcat [B*KL];
__device__ float g_Wcat [4*C*KL];
__device__ float g_bcat [4*C];
__device__ float g_gates[B*4*C];
__device__ float g_hst  [B*C];
__device__ float g_cst  [B*C];
__device__ float g_Paddr[B*NADDR];
__device__ float g_Pea  [B*NEA];
__device__ float g_k    [8*B*M];
__device__ float g_knorm[8*B];
__device__ float g_beta [8*B];
__device__ float g_gate [8*B];
__device__ float g_sv   [8*B*3];
__device__ float g_gamma[8*B];
__device__ float g_e    [4*B*M];
__device__ float g_a    [4*B*M];
__device__ float g_w    [7*BN_];      // final weights heads 0..6 (head 7 dead)
__device__ float g_dot  [2*BN_];
__device__ float g_nrm  [BN_];
__device__ float g_reads[4*B*M];
__device__ float g_state[B*(C+H*M)];

__device__ __forceinline__ float sigmoidf_(float x){ return 1.f/(1.f+expf(-x)); }
__device__ __forceinline__ float softplusf_(float x){ return x>20.f ? x : log1pf(expf(x)); }

// ---- small builders ----
__global__ void k_build_x(const float* __restrict__ ind, const float* __restrict__ prd,
                          const float* __restrict__ h0){
    int idx = blockIdx.x*blockDim.x + threadIdx.x;
    if (idx >= B*KL) return;
    int b = idx / KL, j = idx % KL;
    float v;
    if (j < INP)            v = ind[b*INP + j];
    else if (j < XPART) {   int r = j - INP; v = prd[(r/M)*B*M + b*M + (r%M)]; }
    else                    v = h0[b*C + (j - XPART)];
    g_xcat[idx] = v;
}

__global__ void k_build_W(const float* __restrict__ W_ih, const float* __restrict__ W_hh,
                          const float* __restrict__ b_ih, const float* __restrict__ b_hh){
    int idx = blockIdx.x*blockDim.x + threadIdx.x;
    if (idx >= 4*C*KL) return;
    int j = idx / KL, kk = idx % KL;
    g_Wcat[idx] = (kk < XPART) ? W_ih[j*XPART + kk] : W_hh[j*C + (kk - XPART)];
    if (kk == 0) g_bcat[j] = b_ih[j] + b_hh[j];
}

__global__ void k_build_state(){
    int idx = blockIdx.x*blockDim.x + threadIdx.x;
    if (idx >= B*(C+H*M)) return;
    int b = idx / (C+H*M), j = idx % (C+H*M);
    float v;
    if (j < C) v = g_hst[b*C + j];
    else { int r = j - C; v = g_reads[(r/M)*B*M + b*M + (r%M)]; }
    g_state[idx] = v;
}

// ---- generic tiled GEMM: out[Mo,No] = A[Mo,K] @ W[No,K]^T + bias, optional sigmoid ----
__global__ void k_gemm(const float* __restrict__ A, const float* __restrict__ W,
                       const float* __restrict__ bias, float* __restrict__ out,
                       int Mo, int No, int K, int act){
    __shared__ float As[64][16];
    __shared__ float Ws[64][17];
    int tx = threadIdx.x & 15, ty = threadIdx.x >> 4;
    int bm = blockIdx.y*64, bn = blockIdx.x*64;
    float acc[4][4] = {};
    for (int kb = 0; kb < K; kb += 16){
        #pragma unroll
        for (int r = 0; r < 4; r++){
            int idx = threadIdx.x + r*256;
            int i = idx >> 4, k = idx & 15;
            As[i][k] = A[(size_t)(bm+i)*K + kb + k];
            int j = bn + i;
            Ws[i][k] = (j < No) ? W[(size_t)j*K + kb + k] : 0.f;
        }
        __syncthreads();
        #pragma unroll
        for (int k = 0; k < 16; k++){
            float av[4], wv[4];
            #pragma unroll
            for (int i = 0; i < 4; i++) av[i] = As[ty*4+i][k];
            #pragma unroll
            for (int j = 0; j < 4; j++) wv[j] = Ws[tx*4+j][k];
            #pragma unroll
            for (int i = 0; i < 4; i++)
                #pragma unroll
                for (int j = 0; j < 4; j++) acc[i][j] += av[i]*wv[j];
        }
        __syncthreads();
    }
    #pragma unroll
    for (int i = 0; i < 4; i++){
        int m = bm + ty*4 + i;
        #pragma unroll
        for (int j = 0; j < 4; j++){
            int n = bn + tx*4 + j;
            if (n < No){
                float v = acc[i][j] + bias[n];
                if (act == 1) v = sigmoidf_(v);
                out[(size_t)m*No + n] = v;
            }
        }
    }
}

// ---- LSTM cell pointwise ----
__global__ void k_lstm(const float* __restrict__ c0){
    int idx = blockIdx.x*blockDim.x + threadIdx.x;
    if (idx >= B*C) return;
    int b = idx / C, ci = idx % C;
    const float* gr = g_gates + (size_t)b*4*C;
    float ig = gr[ci], fg = gr[C+ci], gg = gr[2*C+ci], og = gr[3*C+ci];
    float cn = sigmoidf_(fg)*c0[idx] + sigmoidf_(ig)*tanhf(gg);
    g_cst[idx] = cn;
    g_hst[idx] = sigmoidf_(og)*tanhf(cn);
}

// ---- per-head addressing params (+ zero read accumulators) ----
__global__ void k_head_params(){
    int b = blockIdx.x, hi = blockIdx.y, t = threadIdx.x;   // 64 threads
    const float* pa = g_Paddr + (size_t)b*NADDR + hi*70;
    float kv = tanhf(pa[t]);
    g_k[(size_t)(hi*B + b)*M + t] = kv;
    float sq = kv*kv;
    #pragma unroll
    for (int o = 16; o; o >>= 1) sq += __shfl_xor_sync(0xffffffffu, sq, o);
    __shared__ float sh[2];
    if ((t & 31) == 0) sh[t >> 5] = sq;
    __syncthreads();
    if (t == 0){
        g_knorm[hi*B + b] = sqrtf(sh[0] + sh[1]);
        g_beta [hi*B + b] = softplusf_(pa[64]);
        g_gate [hi*B + b] = sigmoidf_(pa[65]);
        float p0 = pa[66], p1 = pa[67], p2 = pa[68];
        float mx = fmaxf(p0, fmaxf(p1, p2));
        float e0 = expf(p0-mx), e1 = expf(p1-mx), e2 = expf(p2-mx);
        float ssum = e0 + e1 + e2;
        g_sv[(hi*B+b)*3+0] = e0/ssum;
        g_sv[(hi*B+b)*3+1] = e1/ssum;
        g_sv[(hi*B+b)*3+2] = e2/ssum;
        g_gamma[hi*B + b] = 1.f + softplusf_(pa[69]);
    }
    if (hi & 1){
        int j = hi >> 1;
        const float* pe = g_Pea + (size_t)b*NEA + j*128;
        g_e[(size_t)j*B*M + b*M + t] = sigmoidf_(pe[t]);
        g_a[(size_t)j*B*M + b*M + t] = tanhf(pe[64+t]);
    }
    if (hi < 4) g_reads[(size_t)hi*B*M + b*M + t] = 0.f;
}

// ---- block reduction helpers (256 threads) ----
__device__ __forceinline__ float blk_max_(float v, float* sh){
    #pragma unroll
    for (int o = 16; o; o >>= 1) v = fmaxf(v, __shfl_xor_sync(0xffffffffu, v, o));
    int w = threadIdx.x >> 5;
    if ((threadIdx.x & 31) == 0) sh[w] = v;
    __syncthreads();
    if (threadIdx.x < 8){
        v = sh[threadIdx.x];
        #pragma unroll
        for (int o = 4; o; o >>= 1) v = fmaxf(v, __shfl_xor_sync(0xffu, v, o));
        if (threadIdx.x == 0) sh[0] = v;
    }
    __syncthreads();
    v = sh[0];
    __syncthreads();
    return v;
}
__device__ __forceinline__ float blk_sum_(float v, float* sh){
    #pragma unroll
    for (int o = 16; o; o >>= 1) v += __shfl_xor_sync(0xffffffffu, v, o);
    int w = threadIdx.x >> 5;
    if ((threadIdx.x & 31) == 0) sh[w] = v;
    __syncthreads();
    if (threadIdx.x < 8){
        v = sh[threadIdx.x];
        #pragma unroll
        for (int o = 4; o; o >>= 1) v += __shfl_xor_sync(0xffu, v, o);
        if (threadIdx.x == 0) sh[0] = v;
    }
    __syncthreads();
    v = sh[0];
    __syncthreads();
    return v;
}

// ---- addressing weights: softmax / interpolate / shift / sharpen ----
// grid (B, nheads), block 256. head = hibase + blockIdx.y, dot slot = blockIdx.y
__global__ void k_weights(int hibase, const float* __restrict__ prevw){
    int b = blockIdx.x;
    int hi = hibase + blockIdx.y;
    int slot = blockIdx.y;
    __shared__ float swg[N];
    __shared__ float sred[8];
    const float* dp = g_dot + (size_t)slot*BN_ + (size_t)b*N;
    const float* np = g_nrm + (size_t)b*N;
    const float* pw = prevw + (size_t)hi*BN_ + (size_t)b*N;
    float beta = g_beta[hi*B+b], gate = g_gate[hi*B+b];
    float kn = g_knorm[hi*B+b],  gam  = g_gamma[hi*B+b];
    float s0 = g_sv[(hi*B+b)*3+0], s1 = g_sv[(hi*B+b)*3+1], s2 = g_sv[(hi*B+b)*3+2];

    float sc[16];
    float mx = -1e30f;
    #pragma unroll
    for (int t = 0; t < 16; t++){
        int i = threadIdx.x + t*256;
        float v = beta * dp[i] / (np[i]*kn + EPS);
        sc[t] = v; mx = fmaxf(mx, v);
    }
    mx = blk_max_(mx, sred);
    float ls = 0.f;
    #pragma unroll
    for (int t = 0; t < 16; t++){ sc[t] = expf(sc[t]-mx); ls += sc[t]; }
    float tot = blk_sum_(ls, sred);
    float inv = 1.f / tot;
    #pragma unroll
    for (int t = 0; t < 16; t++){
        int i = threadIdx.x + t*256;
        swg[i] = gate*sc[t]*inv + (1.f-gate)*pw[i];
    }
    __syncthreads();
    float lp[16]; float ls2 = 0.f;
    #pragma unroll
    for (int t = 0; t < 16; t++){
        int i = threadIdx.x + t*256;
        float ws = s0*swg[(i+N-1)&(N-1)] + s1*swg[i] + s2*swg[(i+1)&(N-1)];
        float wp = powf(ws, gam);
        lp[t] = wp; ls2 += wp;
    }
    float tot2 = blk_sum_(ls2, sred);
    float inv2 = 1.f / (tot2 + EPS);
    #pragma unroll
    for (int t = 0; t < 16; t++){
        int i = threadIdx.x + t*256;
        g_w[(size_t)hi*BN_ + (size_t)b*N + i] = lp[t]*inv2;
    }
}

// ---- the memory pass: reads ORIGINAL memory, recomputes write chain in regs ----
// PASS 0: dots(h0,h1)+norm; PASS p in 1..3: apply p-1 writes, read accum, 1 more
// write, dots; PASS 4: apply 3 writes, read accum only.
template<int PASS>
__global__ void k_pass(const float* __restrict__ mem){
    constexpr int NPRE  = (PASS >= 1) ? (PASS-1) : 0;
    constexpr int NPOST = (PASS >= 1 && PASS <= 3) ? 1 : 0;
    constexpr int NAPP  = NPRE + NPOST;
    constexpr bool HASR = (PASS >= 1);
    constexpr int NDOT  = (PASS == 4) ? 0 : ((PASS == 3) ? 1 : 2);
    constexpr int RSLOT = NPRE;
    constexpr int RHEAD = 2*NPRE;
    constexpr int KB    = 2*PASS;
    constexpr int CHUNK = 256, RPB = 16, ITERS = CHUNK/RPB;

    const int b   = blockIdx.y;
    const int n0  = blockIdx.x * CHUNK;
    const int tid = threadIdx.x;
    const int lane = tid & 15, rg = tid >> 4;

    __shared__ float4 skA[16], skB[16];
    __shared__ float4 sE[3][16], sA[3][16];
    if (tid < 16){
        if (NDOT >= 1) skA[tid] = ((const float4*)(g_k + (size_t)(KB  )*B*M + b*M))[tid];
        if (NDOT >= 2) skB[tid] = ((const float4*)(g_k + (size_t)(KB+1)*B*M + b*M))[tid];
        #pragma unroll
        for (int j = 0; j < NAPP; j++){
            sE[j][tid] = ((const float4*)(g_e + (size_t)j*B*M + b*M))[tid];
            sA[j][tid] = ((const float4*)(g_a + (size_t)j*B*M + b*M))[tid];
        }
    }
    __syncthreads();

    const float4* mrow = (const float4*)mem + (size_t)b*N*(M/4);
    float4 racc = make_float4(0.f,0.f,0.f,0.f);

    #pragma unroll 4
    for (int it = 0; it < ITERS; ++it){
        int n = n0 + it*RPB + rg;
        float4 m = mrow[(size_t)n*(M/4) + lane];
        size_t wi = (size_t)b*N + n;
        #pragma unroll
        for (int j = 0; j < NPRE; j++){
            float wv = g_w[(size_t)(2*j+1)*BN_ + wi];
            float4 e = sE[j][lane], a = sA[j][lane];
            m.x = fmaf(wv, fmaf(-m.x, e.x, a.x), m.x);
            m.y = fmaf(wv, fmaf(-m.y, e.y, a.y), m.y);
            m.z = fmaf(wv, fmaf(-m.z, e.z, a.z), m.z);
            m.w = fmaf(wv, fmaf(-m.w, e.w, a.w), m.w);
        }
        if (HASR){
            float wr = g_w[(size_t)RHEAD*BN_ + wi];
            racc.x = fmaf(wr, m.x, racc.x);
            racc.y = fmaf(wr, m.y, racc.y);
            racc.z = fmaf(wr, m.z, racc.z);
            racc.w = fmaf(wr, m.w, racc.w);
        }
        #pragma unroll
        for (int j = NPRE; j < NAPP; j++){
            float wv = g_w[(size_t)(2*j+1)*BN_ + wi];
            float4 e = sE[j][lane], a = sA[j][lane];
            m.x = fmaf(wv, fmaf(-m.x, e.x, a.x), m.x);
            m.y = fmaf(wv, fmaf(-m.y, e.y, a.y), m.y);
            m.z = fmaf(wv, fmaf(-m.z, e.z, a.z), m.z);
            m.w = fmaf(wv, fmaf(-m.w, e.w, a.w), m.w);
        }
        if (NDOT >= 1){
            float4 kA = skA[lane];
            float dA = m.x*kA.x + m.y*kA.y + m.z*kA.z + m.w*kA.w;
            float ss = m.x*m.x + m.y*m.y + m.z*m.z + m.w*m.w;
            float dB = 0.f;
            if (NDOT >= 2){
                float4 kB2 = skB[lane];
                dB = m.x*kB2.x + m.y*kB2.y + m.z*kB2.z + m.w*kB2.w;
            }
            #pragma unroll
            for (int o = 1; o < 16; o <<= 1){
                dA += __shfl_xor_sync(0xffffffffu, dA, o);
                ss += __shfl_xor_sync(0xffffffffu, ss, o);
                if (NDOT >= 2) dB += __shfl_xor_sync(0xffffffffu, dB, o);
            }
            if (lane == 0){
                g_dot[wi] = dA;
                if (NDOT >= 2) g_dot[BN_ + wi] = dB;
                g_nrm[wi] = sqrtf(ss);
            }
        }
    }
    if (HASR){
        __shared__ float sr[16][64];
        *((float4*)&sr[rg][lane*4]) = racc;
        __syncthreads();
        if (tid < 64){
            float s = 0.f;
            #pragma unroll
            for (int r = 0; r < 16; r++) s += sr[r][tid];
            atomicAdd(&g_reads[(size_t)RSLOT*B*M + b*M + tid], s);
        }
    }
}

extern "C" void kernel_launch(void* const* d_in, const int* in_sizes, int n_in,
                              void* d_out, int out_size){
    const float* in_data = (const float*)d_in[0];
    const float* memory  = (const float*)d_in[1];
    const float* h0      = (const float*)d_in[2];
    const float* c0      = (const float*)d_in[3];
    const float* prevw   = (const float*)d_in[4];
    const float* prevr   = (const float*)d_in[5];
    const float* W_ih    = (const float*)d_in[6];
    const float* b_ih    = (const float*)d_in[7];
    const float* W_hh    = (const float*)d_in[8];
    const float* b_hh    = (const float*)d_in[9];
    const float* W_out   = (const float*)d_in[10];
    const float* b_out   = (const float*)d_in[11];
    const float* W_addr  = (const float*)d_in[12];
    const float* b_addr  = (const float*)d_in[13];
    const float* W_ea    = (const float*)d_in[14];
    const float* b_ea    = (const float*)d_in[15];
    float* out = (float*)d_out;

    float *p_xcat, *p_W, *p_b, *p_g, *p_c, *p_pa, *p_pe, *p_st;
    cudaGetSymbolAddress((void**)&p_xcat, g_xcat);
    cudaGetSymbolAddress((void**)&p_W,    g_Wcat);
    cudaGetSymbolAddress((void**)&p_b,    g_bcat);
    cudaGetSymbolAddress((void**)&p_g,    g_gates);
    cudaGetSymbolAddress((void**)&p_c,    g_cst);
    cudaGetSymbolAddress((void**)&p_pa,   g_Paddr);
    cudaGetSymbolAddress((void**)&p_pe,   g_Pea);
    cudaGetSymbolAddress((void**)&p_st,   g_state);

    // controller
    k_build_x<<<(B*KL + 255)/256, 256>>>(in_data, prevr, h0);
    k_build_W<<<(4*C*KL + 255)/256, 256>>>(W_ih, W_hh, b_ih, b_hh);
    k_gemm<<<dim3(4*C/64, B/64), 256>>>(p_xcat, p_W, p_b, p_g, B, 4*C, KL, 0);
    k_lstm<<<(B*C + 255)/256, 256>>>(c0);

    // head parameter projections (depend only on c)
    k_gemm<<<dim3((NADDR+63)/64, B/64), 256>>>(p_c, W_addr, b_addr, p_pa, B, NADDR, C, 0);
    k_gemm<<<dim3(NEA/64, B/64), 256>>>(p_c, W_ea, b_ea, p_pe, B, NEA, C, 0);
    k_head_params<<<dim3(B, 8), 64>>>();

    // memory passes with interleaved weight computations
    dim3 pg(N/256, B);
    k_pass<0><<<pg, 256>>>(memory);
    k_weights<<<dim3(B,2), 256>>>(0, prevw);
    k_pass<1><<<pg, 256>>>(memory);
    k_weights<<<dim3(B,2), 256>>>(2, prevw);
    k_pass<2><<<pg, 256>>>(memory);
    k_weights<<<dim3(B,2), 256>>>(4, prevw);
    k_pass<3><<<pg, 256>>>(memory);
    k_weights<<<dim3(B,1), 256>>>(6, prevw);
    k_pass<4><<<pg, 256>>>(memory);

    // output
    k_build_state<<<(B*(C+H*M) + 255)/256, 256>>>();
    k_gemm<<<dim3(1, B/64), 256>>>(p_st, W_out, b_out, out, B, OUTD, C+H*M, 1);
}

// round 2
// speedup vs baseline: 1.0403x; 1.0403x over previous
#include <cuda_runtime.h>
#include <cuda_fp16.h>
#include <math.h>

// ---- problem constants ----
constexpr int B   = 256;
constexpr int N   = 4096;
constexpr int M   = 64;
constexpr int C   = 512;
constexpr int H   = 4;
constexpr int INP = 64;
constexpr int OUTD= 64;
constexpr int XPART = INP + H*M;      // 320
constexpr int KL    = XPART + C;      // 832
constexpr int NADDR = 2*H*(M+6);      // 560
constexpr int NEA   = H*2*M;          // 512
constexpr int NPROJ = NADDR + NEA;    // 1072
constexpr int BN_   = B*N;            // 1048576
constexpr float EPS = 1e-8f;

// ---- scratch (device globals: allocation-free) ----
__device__ float  g_xcat [B*KL];
__device__ float  g_Wcat [4*C*KL];
__device__ float  g_bcat [4*C];
__device__ float  g_gates[B*4*C];
__device__ float  g_hst  [B*C];
__device__ float  g_cst  [B*C];
__device__ float  g_P    [B*NPROJ];
__device__ float  g_k    [8*B*M];
__device__ float  g_knorm[8*B];
__device__ float  g_beta [8*B];
__device__ float  g_gate [8*B];
__device__ float  g_sv   [8*B*3];
__device__ float  g_gamma[8*B];
__device__ float  g_e    [4*B*M];
__device__ float  g_a    [4*B*M];
__device__ float  g_w    [7*BN_];      // final weights heads 0..6 (head 7 dead)
__device__ float  g_dot  [2*BN_];
__device__ float  g_nrm  [BN_];
__device__ float  g_reads[4*B*M];
__device__ __half g_mem16[(size_t)B*N*M];   // fp16 image of original memory

__device__ __forceinline__ float sigmoidf_(float x){ return 1.f/(1.f+__expf(-x)); }
__device__ __forceinline__ float softplusf_(float x){ return x>20.f ? x : log1pf(__expf(x)); }

// ---- fused builder: xcat + Wcat + bcat ----
__global__ void k_prep(const float* __restrict__ ind, const float* __restrict__ prd,
                       const float* __restrict__ h0,
                       const float* __restrict__ W_ih, const float* __restrict__ W_hh,
                       const float* __restrict__ b_ih, const float* __restrict__ b_hh){
    int idx = blockIdx.x*blockDim.x + threadIdx.x;
    if (idx < B*KL){
        int b = idx / KL, j = idx % KL;
        float v;
        if (j < INP)            v = ind[b*INP + j];
        else if (j < XPART) {   int r = j - INP; v = prd[(r/M)*B*M + b*M + (r%M)]; }
        else                    v = h0[b*C + (j - XPART)];
        g_xcat[idx] = v;
    }
    int idx2 = idx - B*KL;
    if (idx2 >= 0 && idx2 < 4*C*KL){
        int j = idx2 / KL, kk = idx2 % KL;
        g_Wcat[idx2] = (kk < XPART) ? W_ih[j*XPART + kk] : W_hh[j*C + (kk - XPART)];
        if (kk == 0) g_bcat[j] = b_ih[j] + b_hh[j];
    }
}

// ---- generic tiled GEMM: out[Mo,No] = A[Mo,K] @ W[No,K]^T + bias ----
__global__ void k_gemm(const float* __restrict__ A, const float* __restrict__ W,
                       const float* __restrict__ bias, float* __restrict__ out,
                       int Mo, int No, int K){
    __shared__ float As[64][16];
    __shared__ float Ws[64][17];
    int tx = threadIdx.x & 15, ty = threadIdx.x >> 4;
    int bm = blockIdx.y*64, bn = blockIdx.x*64;
    float acc[4][4] = {};
    for (int kb = 0; kb < K; kb += 16){
        #pragma unroll
        for (int r = 0; r < 4; r++){
            int idx = threadIdx.x + r*256;
            int i = idx >> 4, k = idx & 15;
            As[i][k] = A[(size_t)(bm+i)*K + kb + k];
            int j = bn + i;
            Ws[i][k] = (j < No) ? W[(size_t)j*K + kb + k] : 0.f;
        }
        __syncthreads();
        #pragma unroll
        for (int k = 0; k < 16; k++){
            float av[4], wv[4];
            #pragma unroll
            for (int i = 0; i < 4; i++) av[i] = As[ty*4+i][k];
            #pragma unroll
            for (int j = 0; j < 4; j++) wv[j] = Ws[tx*4+j][k];
            #pragma unroll
            for (int i = 0; i < 4; i++)
                #pragma unroll
                for (int j = 0; j < 4; j++) acc[i][j] += av[i]*wv[j];
        }
        __syncthreads();
    }
    #pragma unroll
    for (int i = 0; i < 4; i++){
        int m = bm + ty*4 + i;
        #pragma unroll
        for (int j = 0; j < 4; j++){
            int n = bn + tx*4 + j;
            if (n < No) out[(size_t)m*No + n] = acc[i][j] + bias[n];
        }
    }
}

// ---- fused projection GEMM: rows [0,560) from W_addr, [560,1072) from W_ea ----
__global__ void k_gemm_proj(const float* __restrict__ A,
                            const float* __restrict__ W1, const float* __restrict__ b1,
                            const float* __restrict__ W2, const float* __restrict__ b2,
                            float* __restrict__ out){
    constexpr int K = C, No = NPROJ;
    __shared__ float As[64][16];
    __shared__ float Ws[64][17];
    int tx = threadIdx.x & 15, ty = threadIdx.x >> 4;
    int bm = blockIdx.y*64, bn = blockIdx.x*64;
    float acc[4][4] = {};
    for (int kb = 0; kb < K; kb += 16){
        #pragma unroll
        for (int r = 0; r < 4; r++){
            int idx = threadIdx.x + r*256;
            int i = idx >> 4, k = idx & 15;
            As[i][k] = A[(size_t)(bm+i)*K + kb + k];
            int j = bn + i;
            float wv = 0.f;
            if (j < NADDR)      wv = W1[(size_t)j*K + kb + k];
            else if (j < No)    wv = W2[(size_t)(j-NADDR)*K + kb + k];
            Ws[i][k] = wv;
        }
        __syncthreads();
        #pragma unroll
        for (int k = 0; k < 16; k++){
            float av[4], wv[4];
            #pragma unroll
            for (int i = 0; i < 4; i++) av[i] = As[ty*4+i][k];
            #pragma unroll
            for (int j = 0; j < 4; j++) wv[j] = Ws[tx*4+j][k];
            #pragma unroll
            for (int i = 0; i < 4; i++)
                #pragma unroll
                for (int j = 0; j < 4; j++) acc[i][j] += av[i]*wv[j];
        }
        __syncthreads();
    }
    #pragma unroll
    for (int i = 0; i < 4; i++){
        int m = bm + ty*4 + i;
        #pragma unroll
        for (int j = 0; j < 4; j++){
            int n = bn + tx*4 + j;
            if (n < No){
                float bb = (n < NADDR) ? b1[n] : b2[n - NADDR];
                out[(size_t)m*No + n] = acc[i][j] + bb;
            }
        }
    }
}

// ---- output GEMM with A gathered from [h | reads], sigmoid epilogue ----
__global__ void k_gemm_out(const float* __restrict__ W, const float* __restrict__ bias,
                           float* __restrict__ out){
    constexpr int K = C + H*M, No = OUTD;
    __shared__ float As[64][16];
    __shared__ float Ws[64][17];
    int tx = threadIdx.x & 15, ty = threadIdx.x >> 4;
    int bm = blockIdx.y*64;
    float acc[4][4] = {};
    for (int kb = 0; kb < K; kb += 16){
        #pragma unroll
        for (int r = 0; r < 4; r++){
            int idx = threadIdx.x + r*256;
            int i = idx >> 4, k = idx & 15;
            int m = bm + i, kk = kb + k;
            float av;
            if (kk < C) av = g_hst[(size_t)m*C + kk];
            else { int rr = kk - C; av = g_reads[(size_t)(rr/M)*B*M + m*M + (rr%M)]; }
            As[i][k] = av;
            Ws[i][k] = (i < No) ? W[(size_t)i*K + kb + k] : 0.f;
        }
        __syncthreads();
        #pragma unroll
        for (int k = 0; k < 16; k++){
            float av[4], wv[4];
            #pragma unroll
            for (int i = 0; i < 4; i++) av[i] = As[ty*4+i][k];
            #pragma unroll
            for (int j = 0; j < 4; j++) wv[j] = Ws[tx*4+j][k];
            #pragma unroll
            for (int i = 0; i < 4; i++)
                #pragma unroll
                for (int j = 0; j < 4; j++) acc[i][j] += av[i]*wv[j];
        }
        __syncthreads();
    }
    #pragma unroll
    for (int i = 0; i < 4; i++){
        int m = bm + ty*4 + i;
        #pragma unroll
        for (int j = 0; j < 4; j++){
            int n = tx*4 + j;
            if (n < No) out[(size_t)m*No + n] = sigmoidf_(acc[i][j] + bias[n]);
        }
    }
}

// ---- LSTM cell pointwise ----
__global__ void k_lstm(const float* __restrict__ c0){
    int idx = blockIdx.x*blockDim.x + threadIdx.x;
    if (idx >= B*C) return;
    int b = idx / C, ci = idx % C;
    const float* gr = g_gates + (size_t)b*4*C;
    float ig = gr[ci], fg = gr[C+ci], gg = gr[2*C+ci], og = gr[3*C+ci];
    float cn = sigmoidf_(fg)*c0[idx] + sigmoidf_(ig)*tanhf(gg);
    g_cst[idx] = cn;
    g_hst[idx] = sigmoidf_(og)*tanhf(cn);
}

// ---- per-head addressing params (+ zero read accumulators) ----
__global__ void k_head_params(){
    int b = blockIdx.x, hi = blockIdx.y, t = threadIdx.x;   // 64 threads
    const float* pa = g_P + (size_t)b*NPROJ + hi*70;
    float kv = tanhf(pa[t]);
    g_k[(size_t)(hi*B + b)*M + t] = kv;
    float sq = kv*kv;
    #pragma unroll
    for (int o = 16; o; o >>= 1) sq += __shfl_xor_sync(0xffffffffu, sq, o);
    __shared__ float sh[2];
    if ((t & 31) == 0) sh[t >> 5] = sq;
    __syncthreads();
    if (t == 0){
        g_knorm[hi*B + b] = sqrtf(sh[0] + sh[1]);
        g_beta [hi*B + b] = softplusf_(pa[64]);
        g_gate [hi*B + b] = sigmoidf_(pa[65]);
        float p0 = pa[66], p1 = pa[67], p2 = pa[68];
        float mx = fmaxf(p0, fmaxf(p1, p2));
        float e0 = __expf(p0-mx), e1 = __expf(p1-mx), e2 = __expf(p2-mx);
        float ssum = e0 + e1 + e2;
        g_sv[(hi*B+b)*3+0] = e0/ssum;
        g_sv[(hi*B+b)*3+1] = e1/ssum;
        g_sv[(hi*B+b)*3+2] = e2/ssum;
        g_gamma[hi*B + b] = 1.f + softplusf_(pa[69]);
    }
    if (hi & 1){
        int j = hi >> 1;
        const float* pe = g_P + (size_t)b*NPROJ + NADDR + j*128;
        g_e[(size_t)j*B*M + b*M + t] = sigmoidf_(pe[t]);
        g_a[(size_t)j*B*M + b*M + t] = tanhf(pe[64+t]);
    }
    if (hi < 4) g_reads[(size_t)hi*B*M + b*M + t] = 0.f;
}

// ---- block reduction helpers (256 threads) ----
__device__ __forceinline__ float blk_max_(float v, float* sh){
    #pragma unroll
    for (int o = 16; o; o >>= 1) v = fmaxf(v, __shfl_xor_sync(0xffffffffu, v, o));
    int w = threadIdx.x >> 5;
    if ((threadIdx.x & 31) == 0) sh[w] = v;
    __syncthreads();
    if (threadIdx.x < 8){
        v = sh[threadIdx.x];
        #pragma unroll
        for (int o = 4; o; o >>= 1) v = fmaxf(v, __shfl_xor_sync(0xffu, v, o));
        if (threadIdx.x == 0) sh[0] = v;
    }
    __syncthreads();
    v = sh[0];
    __syncthreads();
    return v;
}
__device__ __forceinline__ float blk_sum_(float v, float* sh){
    #pragma unroll
    for (int o = 16; o; o >>= 1) v += __shfl_xor_sync(0xffffffffu, v, o);
    int w = threadIdx.x >> 5;
    if ((threadIdx.x & 31) == 0) sh[w] = v;
    __syncthreads();
    if (threadIdx.x < 8){
        v = sh[threadIdx.x];
        #pragma unroll
        for (int o = 4; o; o >>= 1) v += __shfl_xor_sync(0xffu, v, o);
        if (threadIdx.x == 0) sh[0] = v;
    }
    __syncthreads();
    v = sh[0];
    __syncthreads();
    return v;
}

// ---- addressing weights: softmax / interpolate / shift / sharpen ----
__global__ void k_weights(int hibase, const float* __restrict__ prevw){
    int b = blockIdx.x;
    int hi = hibase + blockIdx.y;
    int slot = blockIdx.y;
    __shared__ float swg[N];
    __shared__ float sred[8];
    const float* dp = g_dot + (size_t)slot*BN_ + (size_t)b*N;
    const float* np = g_nrm + (size_t)b*N;
    const float* pw = prevw + (size_t)hi*BN_ + (size_t)b*N;
    float beta = g_beta[hi*B+b], gate = g_gate[hi*B+b];
    float kn = g_knorm[hi*B+b],  gam  = g_gamma[hi*B+b];
    float s0 = g_sv[(hi*B+b)*3+0], s1 = g_sv[(hi*B+b)*3+1], s2 = g_sv[(hi*B+b)*3+2];

    float sc[16];
    float mx = -1e30f;
    #pragma unroll
    for (int t = 0; t < 16; t++){
        int i = threadIdx.x + t*256;
        float v = beta * dp[i] / (np[i]*kn + EPS);
        sc[t] = v; mx = fmaxf(mx, v);
    }
    mx = blk_max_(mx, sred);
    float ls = 0.f;
    #pragma unroll
    for (int t = 0; t < 16; t++){ sc[t] = __expf(sc[t]-mx); ls += sc[t]; }
    float tot = blk_sum_(ls, sred);
    float inv = 1.f / tot;
    #pragma unroll
    for (int t = 0; t < 16; t++){
        int i = threadIdx.x + t*256;
        swg[i] = gate*sc[t]*inv + (1.f-gate)*pw[i];
    }
    __syncthreads();
    float lp[16]; float ls2 = 0.f;
    #pragma unroll
    for (int t = 0; t < 16; t++){
        int i = threadIdx.x + t*256;
        float ws = s0*swg[(i+N-1)&(N-1)] + s1*swg[i] + s2*swg[(i+1)&(N-1)];
        float wp = __powf(ws, gam);
        lp[t] = wp; ls2 += wp;
    }
    float tot2 = blk_sum_(ls2, sred);
    float inv2 = 1.f / (tot2 + EPS);
    #pragma unroll
    for (int t = 0; t < 16; t++){
        int i = threadIdx.x + t*256;
        g_w[(size_t)hi*BN_ + (size_t)b*N + i] = lp[t]*inv2;
    }
}

// ---- PASS 0: read fp32 memory; write fp16 image; dots(k0,k1) + norms ----
__global__ void k_pass0(const float* __restrict__ mem){
    constexpr int CHUNK = 256, RPB = 16, ITERS = CHUNK/RPB;
    const int b   = blockIdx.y;
    const int n0  = blockIdx.x * CHUNK;
    const int tid = threadIdx.x;
    const int lane = tid & 15, rg = tid >> 4;

    __shared__ float4 skA[16], skB[16];
    if (tid < 16){
        skA[tid] = ((const float4*)(g_k + (size_t)0*B*M + b*M))[tid];
        skB[tid] = ((const float4*)(g_k + (size_t)1*B*M + b*M))[tid];
    }
    __syncthreads();

    const float4* mrow = (const float4*)mem + (size_t)b*N*(M/4);
    uint2* orow = (uint2*)g_mem16 + ((size_t)b*N)*(M/4);   // 16 uint2 per row

    #pragma unroll 4
    for (int it = 0; it < ITERS; ++it){
        int n = n0 + it*RPB + rg;
        float4 m = mrow[(size_t)n*(M/4) + lane];
        // fp16 store
        __half2 ha = __floats2half2_rn(m.x, m.y);
        __half2 hb = __floats2half2_rn(m.z, m.w);
        uint2 st;
        st.x = *reinterpret_cast<const unsigned*>(&ha);
        st.y = *reinterpret_cast<const unsigned*>(&hb);
        orow[(size_t)n*(M/4) + lane] = st;

        size_t wi = (size_t)b*N + n;
        float4 kA = skA[lane], kB = skB[lane];
        float dA = m.x*kA.x + m.y*kA.y + m.z*kA.z + m.w*kA.w;
        float dB = m.x*kB.x + m.y*kB.y + m.z*kB.z + m.w*kB.w;
        float ss = m.x*m.x + m.y*m.y + m.z*m.z + m.w*m.w;
        #pragma unroll
        for (int o = 1; o < 16; o <<= 1){
            dA += __shfl_xor_sync(0xffffffffu, dA, o);
            dB += __shfl_xor_sync(0xffffffffu, dB, o);
            ss += __shfl_xor_sync(0xffffffffu, ss, o);
        }
        if (lane == 0){
            g_dot[wi]       = dA;
            g_dot[BN_ + wi] = dB;
            g_nrm[wi]       = sqrtf(ss);
        }
    }
}

// ---- PASSES 1..4: read fp16 image, recompute write chain, dots/reads ----
template<int PASS>
__global__ void k_pass16(){
    constexpr int NPRE  = PASS - 1;
    constexpr int NPOST = (PASS <= 3) ? 1 : 0;
    constexpr int NAPP  = NPRE + NPOST;
    constexpr int NDOT  = (PASS == 4) ? 0 : ((PASS == 3) ? 1 : 2);
    constexpr int RSLOT = NPRE;
    constexpr int RHEAD = 2*NPRE;
    constexpr int KB    = 2*PASS;

    const int b   = blockIdx.y;
    const int n0  = blockIdx.x * 256;
    const int tid = threadIdx.x;
    const int lane = tid & 7, rg = tid >> 3;   // 32 rows/iter, 8 lanes/row

    __shared__ float sk[2][64];
    __shared__ float se[3][64], sa[3][64];
    if (tid < 64){
        if (NDOT >= 1) sk[0][tid] = g_k[(size_t)(KB  )*B*M + b*M + tid];
        if (NDOT >= 2) sk[1][tid] = g_k[(size_t)(KB+1)*B*M + b*M + tid];
        #pragma unroll
        for (int j = 0; j < NAPP; j++){
            se[j][tid] = g_e[(size_t)j*B*M + b*M + tid];
            sa[j][tid] = g_a[(size_t)j*B*M + b*M + tid];
        }
    }
    __syncthreads();

    // hoist per-lane constants to registers
    float kr0[8], kr1[8], er[3][8], ar[3][8];
    #pragma unroll
    for (int t = 0; t < 8; t++){
        if (NDOT >= 1) kr0[t] = sk[0][lane*8+t];
        if (NDOT >= 2) kr1[t] = sk[1][lane*8+t];
        #pragma unroll
        for (int j = 0; j < NAPP; j++){ er[j][t] = se[j][lane*8+t]; ar[j][t] = sa[j][lane*8+t]; }
    }

    const uint4* base = (const uint4*)g_mem16 + ((size_t)b*N + n0)*8;   // 8 uint4 per row
    float racc[8];
    #pragma unroll
    for (int t = 0; t < 8; t++) racc[t] = 0.f;

    #pragma unroll
    for (int it = 0; it < 8; ++it){
        int n = n0 + it*32 + rg;
        uint4 raw = base[(size_t)(it*32 + rg)*8 + lane];
        float f[8];
        {
            __half2 h0 = *reinterpret_cast<const __half2*>(&raw.x);
            __half2 h1 = *reinterpret_cast<const __half2*>(&raw.y);
            __half2 h2 = *reinterpret_cast<const __half2*>(&raw.z);
            __half2 h3 = *reinterpret_cast<const __half2*>(&raw.w);
            float2 a0 = __half22float2(h0), a1 = __half22float2(h1);
            float2 a2 = __half22float2(h2), a3 = __half22float2(h3);
            f[0]=a0.x; f[1]=a0.y; f[2]=a1.x; f[3]=a1.y;
            f[4]=a2.x; f[5]=a2.y; f[6]=a3.x; f[7]=a3.y;
        }
        size_t wi = (size_t)b*N + n;
        #pragma unroll
        for (int j = 0; j < NPRE; j++){
            float wv = g_w[(size_t)(2*j+1)*BN_ + wi];
            #pragma unroll
            for (int t = 0; t < 8; t++)
                f[t] = fmaf(wv, fmaf(-f[t], er[j][t], ar[j][t]), f[t]);
        }
        {
            float wr = g_w[(size_t)RHEAD*BN_ + wi];
            #pragma unroll
            for (int t = 0; t < 8; t++) racc[t] = fmaf(wr, f[t], racc[t]);
        }
        #pragma unroll
        for (int j = NPRE; j < NAPP; j++){
            float wv = g_w[(size_t)(2*j+1)*BN_ + wi];
            #pragma unroll
            for (int t = 0; t < 8; t++)
                f[t] = fmaf(wv, fmaf(-f[t], er[j][t], ar[j][t]), f[t]);
        }
        if (NDOT >= 1){
            float dA = 0.f, dB = 0.f, ss = 0.f;
            #pragma unroll
            for (int t = 0; t < 8; t++){
                dA = fmaf(f[t], kr0[t], dA);
                if (NDOT >= 2) dB = fmaf(f[t], kr1[t], dB);
                ss = fmaf(f[t], f[t], ss);
            }
            #pragma unroll
            for (int o = 1; o < 8; o <<= 1){
                dA += __shfl_xor_sync(0xffffffffu, dA, o);
                ss += __shfl_xor_sync(0xffffffffu, ss, o);
                if (NDOT >= 2) dB += __shfl_xor_sync(0xffffffffu, dB, o);
            }
            if (lane == 0){
                g_dot[wi] = dA;
                if (NDOT >= 2) g_dot[BN_ + wi] = dB;
                g_nrm[wi] = sqrtf(ss);
            }
        }
    }
    // block-level read reduction
    __shared__ float sr[32][64];
    #pragma unroll
    for (int t = 0; t < 8; t++) sr[rg][lane*8+t] = racc[t];
    __syncthreads();
    if (tid < 64){
        float s = 0.f;
        #pragma unroll
        for (int r = 0; r < 32; r++) s += sr[r][tid];
        atomicAdd(&g_reads[(size_t)RSLOT*B*M + b*M + tid], s);
    }
}

extern "C" void kernel_launch(void* const* d_in, const int* in_sizes, int n_in,
                              void* d_out, int out_size){
    const float* in_data = (const float*)d_in[0];
    const float* memory  = (const float*)d_in[1];
    const float* h0      = (const float*)d_in[2];
    const float* c0      = (const float*)d_in[3];
    const float* prevw   = (const float*)d_in[4];
    const float* prevr   = (const float*)d_in[5];
    const float* W_ih    = (const float*)d_in[6];
    const float* b_ih    = (const float*)d_in[7];
    const float* W_hh    = (const float*)d_in[8];
    const float* b_hh    = (const float*)d_in[9];
    const float* W_out   = (const float*)d_in[10];
    const float* b_out   = (const float*)d_in[11];
    const float* W_addr  = (const float*)d_in[12];
    const float* b_addr  = (const float*)d_in[13];
    const float* W_ea    = (const float*)d_in[14];
    const float* b_ea    = (const float*)d_in[15];
    float* out = (float*)d_out;

    float *p_xcat, *p_W, *p_b, *p_g, *p_c, *p_P;
    cudaGetSymbolAddress((void**)&p_xcat, g_xcat);
    cudaGetSymbolAddress((void**)&p_W,    g_Wcat);
    cudaGetSymbolAddress((void**)&p_b,    g_bcat);
    cudaGetSymbolAddress((void**)&p_g,    g_gates);
    cudaGetSymbolAddress((void**)&p_c,    g_cst);
    cudaGetSymbolAddress((void**)&p_P,    g_P);

    // controller
    int prep_total = B*KL + 4*C*KL;
    k_prep<<<(prep_total + 255)/256, 256>>>(in_data, prevr, h0, W_ih, W_hh, b_ih, b_hh);
    k_gemm<<<dim3(4*C/64, B/64), 256>>>(p_xcat, p_W, p_b, p_g, B, 4*C, KL);
    k_lstm<<<(B*C + 255)/256, 256>>>(c0);

    // fused head projections (addr + erase/add)
    k_gemm_proj<<<dim3((NPROJ+63)/64, B/64), 256>>>(p_c, W_addr, b_addr, W_ea, b_ea, p_P);
    k_head_params<<<dim3(B, 8), 64>>>();

    // memory passes with interleaved weight computations
    dim3 pg(N/256, B);
    k_pass0<<<pg, 256>>>(memory);
    k_weights<<<dim3(B,2), 256>>>(0, prevw);
    k_pass16<1><<<pg, 256>>>();
    k_weights<<<dim3(B,2), 256>>>(2, prevw);
    k_pass16<2><<<pg, 256>>>();
    k_weights<<<dim3(B,2), 256>>>(4, prevw);
    k_pass16<3><<<pg, 256>>>();
    k_weights<<<dim3(B,1), 256>>>(6, prevw);
    k_pass16<4><<<pg, 256>>>();

    // output
    k_gemm_out<<<dim3(1, B/64), 256>>>(W_out, b_out, out);
}

// round 4
// speedup vs baseline: 1.2147x; 1.1677x over previous
#include <cuda_runtime.h>
#include <cuda_fp16.h>
#include <math.h>

// ---- problem constants ----
constexpr int B   = 256;
constexpr int N   = 4096;
constexpr int M   = 64;
constexpr int C   = 512;
constexpr int H   = 4;
constexpr int INP = 64;
constexpr int OUTD= 64;
constexpr int XPART = INP + H*M;      // 320
constexpr int KL    = XPART + C;      // 832
constexpr int NADDR = 2*H*(M+6);      // 560
constexpr int NEA   = H*2*M;          // 512
constexpr int NPROJ = NADDR + NEA;    // 1072
constexpr int KOUT  = C + H*M;        // 768
constexpr int BN_   = B*N;            // 1048576
constexpr float EPS = 1e-8f;

// ---- scratch (device globals: allocation-free) ----
__device__ float  g_xcat [B*KL];
__device__ float  g_Wcat [4*C*KL];    // interleaved rows: 4*ci + gate
__device__ float  g_bcat [4*C];
__device__ float  g_hst  [B*C];
__device__ float  g_cst  [B*C];
__device__ float  g_P    [B*NPROJ];
__device__ float  g_k    [8*B*M];
__device__ float  g_knorm[8*B];
__device__ float  g_beta [8*B];
__device__ float  g_gate [8*B];
__device__ float  g_sv   [8*B*3];
__device__ float  g_gamma[8*B];
__device__ float  g_e    [4*B*M];
__device__ float  g_a    [4*B*M];
__device__ float  g_w    [7*BN_];
__device__ float  g_dot  [2*BN_];
__device__ float  g_nrm  [BN_];
__device__ float  g_reads[4*B*M];
__device__ __half g_mem16[(size_t)B*N*M];

__device__ __forceinline__ float sigmoidf_(float x){ return 1.f/(1.f+__expf(-x)); }
__device__ __forceinline__ float softplusf_(float x){ return x>20.f ? x : log1pf(__expf(x)); }

__device__ __forceinline__ void cp_async4(void* sdst, const void* gsrc){
    unsigned s = (unsigned)__cvta_generic_to_shared(sdst);
    asm volatile("cp.async.ca.shared.global [%0], [%1], 4;" :: "r"(s), "l"(gsrc));
}
__device__ __forceinline__ void cp_commit(){ asm volatile("cp.async.commit_group;"); }
template<int NG> __device__ __forceinline__ void cp_wait(){ asm volatile("cp.async.wait_group %0;" :: "n"(NG)); }

// ---- fused builder: xcat + interleaved Wcat + bcat ----
__global__ void k_prep(const float* __restrict__ ind, const float* __restrict__ prd,
                       const float* __restrict__ h0,
                       const float* __restrict__ W_ih, const float* __restrict__ W_hh,
                       const float* __restrict__ b_ih, const float* __restrict__ b_hh){
    int idx = blockIdx.x*blockDim.x + threadIdx.x;
    if (idx < B*KL){
        int b = idx / KL, j = idx % KL;
        float v;
        if (j < INP)            v = ind[b*INP + j];
        else if (j < XPART) {   int r = j - INP; v = prd[(r/M)*B*M + b*M + (r%M)]; }
        else                    v = h0[b*C + (j - XPART)];
        g_xcat[idx] = v;
    }
    int idx2 = idx - B*KL;
    if (idx2 >= 0 && idx2 < 4*C*KL){
        int j = idx2 / KL, kk = idx2 % KL;
        int ci = j >> 2, gg = j & 3;
        int src = gg*C + ci;
        g_Wcat[idx2] = (kk < XPART) ? W_ih[(size_t)src*XPART + kk] : W_hh[(size_t)src*C + (kk - XPART)];
        if (kk == 0) g_bcat[j] = b_ih[src] + b_hh[src];
    }
}

// ============ pipelined GEMM: gates + fused LSTM epilogue ============
// BM=64, BN=32, BK=16, 256 threads, thread tile 2x4. Wcat rows interleaved.
__global__ void k_gates(const float* __restrict__ c0){
    constexpr int K = KL, NK = K/16;
    __shared__ float As[2][64][17];
    __shared__ float Ws[2][32][17];
    const int tid = threadIdx.x;
    const int tx = tid & 7, ty = tid >> 3;       // tx: 8 col-groups, ty: 32 row-groups
    const int bn = blockIdx.x*32, bm = blockIdx.y*64;
    const float* A = g_xcat;
    const float* W = g_Wcat;

    auto prefetch = [&](int kb, int buf){
        int k0 = kb*16;
        #pragma unroll
        for (int r = 0; r < 4; r++){
            int idx = tid + r*256;
            int i = idx >> 4, k = idx & 15;
            cp_async4(&As[buf][i][k], &A[(size_t)(bm+i)*K + k0 + k]);
        }
        #pragma unroll
        for (int r = 0; r < 2; r++){
            int idx = tid + r*256;
            int i = idx >> 4, k = idx & 15;
            cp_async4(&Ws[buf][i][k], &W[(size_t)(bn+i)*K + k0 + k]);
        }
    };

    float acc[2][4] = {};
    prefetch(0, 0); cp_commit();
    for (int kb = 0; kb < NK; kb++){
        int cur = kb & 1;
        if (kb+1 < NK){ prefetch(kb+1, cur^1); cp_commit(); cp_wait<1>(); }
        else cp_wait<0>();
        __syncthreads();
        #pragma unroll
        for (int k = 0; k < 16; k++){
            float av0 = As[cur][ty*2+0][k], av1 = As[cur][ty*2+1][k];
            float wv[4];
            #pragma unroll
            for (int j = 0; j < 4; j++) wv[j] = Ws[cur][tx*4+j][k];
            #pragma unroll
            for (int j = 0; j < 4; j++){ acc[0][j] += av0*wv[j]; acc[1][j] += av1*wv[j]; }
        }
        __syncthreads();
    }
    // epilogue: 4 cols of this thread = {i,f,g,o} of channel ci
    int ci = (bn >> 2) + tx;
    #pragma unroll
    for (int i = 0; i < 2; i++){
        int m = bm + ty*2 + i;
        float ig = acc[i][0] + g_bcat[bn + tx*4 + 0];
        float fg = acc[i][1] + g_bcat[bn + tx*4 + 1];
        float gg = acc[i][2] + g_bcat[bn + tx*4 + 2];
        float og = acc[i][3] + g_bcat[bn + tx*4 + 3];
        float cn = sigmoidf_(fg)*c0[(size_t)m*C + ci] + sigmoidf_(ig)*tanhf(gg);
        g_cst[(size_t)m*C + ci] = cn;
        g_hst[(size_t)m*C + ci] = sigmoidf_(og)*tanhf(cn);
    }
}

// ============ pipelined GEMM: fused addr+ea projections ============
__global__ void k_proj(const float* __restrict__ W1, const float* __restrict__ b1,
                       const float* __restrict__ W2, const float* __restrict__ b2){
    constexpr int K = C, NK = K/16, No = NPROJ;
    __shared__ float As[2][64][17];
    __shared__ float Ws[2][32][17];
    const int tid = threadIdx.x;
    const int tx = tid & 7, ty = tid >> 3;
    const int bn = blockIdx.x*32, bm = blockIdx.y*64;
    const float* A = g_cst;

    auto prefetch = [&](int kb, int buf){
        int k0 = kb*16;
        #pragma unroll
        for (int r = 0; r < 4; r++){
            int idx = tid + r*256;
            int i = idx >> 4, k = idx & 15;
            cp_async4(&As[buf][i][k], &A[(size_t)(bm+i)*K + k0 + k]);
        }
        #pragma unroll
        for (int r = 0; r < 2; r++){
            int idx = tid + r*256;
            int i = idx >> 4, k = idx & 15;
            int j = bn + i; if (j > No-1) j = No-1;
            const float* src = (j < NADDR) ? &W1[(size_t)j*K + k0 + k]
                                           : &W2[(size_t)(j-NADDR)*K + k0 + k];
            cp_async4(&Ws[buf][i][k], src);
        }
    };

    float acc[2][4] = {};
    prefetch(0, 0); cp_commit();
    for (int kb = 0; kb < NK; kb++){
        int cur = kb & 1;
        if (kb+1 < NK){ prefetch(kb+1, cur^1); cp_commit(); cp_wait<1>(); }
        else cp_wait<0>();
        __syncthreads();
        #pragma unroll
        for (int k = 0; k < 16; k++){
            float av0 = As[cur][ty*2+0][k], av1 = As[cur][ty*2+1][k];
            float wv[4];
            #pragma unroll
            for (int j = 0; j < 4; j++) wv[j] = Ws[cur][tx*4+j][k];
            #pragma unroll
            for (int j = 0; j < 4; j++){ acc[0][j] += av0*wv[j]; acc[1][j] += av1*wv[j]; }
        }
        __syncthreads();
    }
    #pragma unroll
    for (int i = 0; i < 2; i++){
        int m = bm + ty*2 + i;
        #pragma unroll
        for (int j = 0; j < 4; j++){
            int n = bn + tx*4 + j;
            if (n < No){
                float bb = (n < NADDR) ? b1[n] : b2[n - NADDR];
                g_P[(size_t)m*No + n] = acc[i][j] + bb;
            }
        }
    }
}

// ============ output layer: warp-per-columns GEMV, 1 block per batch row ============
__global__ void k_out(const float* __restrict__ W, const float* __restrict__ bias,
                      float* __restrict__ out){
    const int m = blockIdx.x;
    const int tid = threadIdx.x, lane = tid & 31, wid = tid >> 5;   // 8 warps
    __shared__ float sA[KOUT];
    for (int idx = tid; idx < KOUT; idx += 256){
        float v;
        if (idx < C) v = g_hst[(size_t)m*C + idx];
        else { int r = idx - C; v = g_reads[(size_t)(r>>6)*B*M + m*M + (r&63)]; }
        sA[idx] = v;
    }
    __syncthreads();
    #pragma unroll
    for (int nn = 0; nn < 8; nn++){
        int n = wid*8 + nn;
        const float* wr = &W[(size_t)n*KOUT];
        float s = 0.f;
        #pragma unroll 6
        for (int kk = lane; kk < KOUT; kk += 32) s += sA[kk]*wr[kk];
        #pragma unroll
        for (int o = 16; o; o >>= 1) s += __shfl_xor_sync(0xffffffffu, s, o);
        if (lane == 0) out[(size_t)m*OUTD + n] = sigmoidf_(s + bias[n]);
    }
}

// ---- per-head addressing params (+ zero read accumulators) ----
__global__ void k_head_params(){
    int b = blockIdx.x, hi = blockIdx.y, t = threadIdx.x;   // 64 threads
    const float* pa = g_P + (size_t)b*NPROJ + hi*70;
    float kv = tanhf(pa[t]);
    g_k[(size_t)(hi*B + b)*M + t] = kv;
    float sq = kv*kv;
    #pragma unroll
    for (int o = 16; o; o >>= 1) sq += __shfl_xor_sync(0xffffffffu, sq, o);
    __shared__ float sh[2];
    if ((t & 31) == 0) sh[t >> 5] = sq;
    __syncthreads();
    if (t == 0){
        g_knorm[hi*B + b] = sqrtf(sh[0] + sh[1]);
        g_beta [hi*B + b] = softplusf_(pa[64]);
        g_gate [hi*B + b] = sigmoidf_(pa[65]);
        float p0 = pa[66], p1 = pa[67], p2 = pa[68];
        float mx = fmaxf(p0, fmaxf(p1, p2));
        float e0 = __expf(p0-mx), e1 = __expf(p1-mx), e2 = __expf(p2-mx);
        float ssum = e0 + e1 + e2;
        g_sv[(hi*B+b)*3+0] = e0/ssum;
        g_sv[(hi*B+b)*3+1] = e1/ssum;
        g_sv[(hi*B+b)*3+2] = e2/ssum;
        g_gamma[hi*B + b] = 1.f + softplusf_(pa[69]);
    }
    if (hi & 1){
        int j = hi >> 1;
        const float* pe = g_P + (size_t)b*NPROJ + NADDR + j*128;
        g_e[(size_t)j*B*M + b*M + t] = sigmoidf_(pe[t]);
        g_a[(size_t)j*B*M + b*M + t] = tanhf(pe[64+t]);
    }
    if (hi < 4) g_reads[(size_t)hi*B*M + b*M + t] = 0.f;
}

// ---- block reduction helpers (256 threads) ----
__device__ __forceinline__ float blk_max_(float v, float* sh){
    #pragma unroll
    for (int o = 16; o; o >>= 1) v = fmaxf(v, __shfl_xor_sync(0xffffffffu, v, o));
    int w = threadIdx.x >> 5;
    if ((threadIdx.x & 31) == 0) sh[w] = v;
    __syncthreads();
    if (threadIdx.x < 8){
        v = sh[threadIdx.x];
        #pragma unroll
        for (int o = 4; o; o >>= 1) v = fmaxf(v, __shfl_xor_sync(0xffu, v, o));
        if (threadIdx.x == 0) sh[0] = v;
    }
    __syncthreads();
    v = sh[0];
    __syncthreads();
    return v;
}
__device__ __forceinline__ float blk_sum_(float v, float* sh){
    #pragma unroll
    for (int o = 16; o; o >>= 1) v += __shfl_xor_sync(0xffffffffu, v, o);
    int w = threadIdx.x >> 5;
    if ((threadIdx.x & 31) == 0) sh[w] = v;
    __syncthreads();
    if (threadIdx.x < 8){
        v = sh[threadIdx.x];
        #pragma unroll
        for (int o = 4; o; o >>= 1) v += __shfl_xor_sync(0xffu, v, o);
        if (threadIdx.x == 0) sh[0] = v;
    }
    __syncthreads();
    v = sh[0];
    __syncthreads();
    return v;
}

// ---- addressing weights: softmax / interpolate / shift / sharpen ----
__global__ void k_weights(int hibase, const float* __restrict__ prevw){
    int b = blockIdx.x;
    int hi = hibase + blockIdx.y;
    int slot = blockIdx.y;
    __shared__ float swg[N];
    __shared__ float sred[8];
    const float* dp = g_dot + (size_t)slot*BN_ + (size_t)b*N;
    const float* np = g_nrm + (size_t)b*N;
    const float* pw = prevw + (size_t)hi*BN_ + (size_t)b*N;
    float beta = g_beta[hi*B+b], gate = g_gate[hi*B+b];
    float kn = g_knorm[hi*B+b],  gam  = g_gamma[hi*B+b];
    float s0 = g_sv[(hi*B+b)*3+0], s1 = g_sv[(hi*B+b)*3+1], s2 = g_sv[(hi*B+b)*3+2];

    float sc[16];
    float mx = -1e30f;
    #pragma unroll
    for (int t = 0; t < 16; t++){
        int i = threadIdx.x + t*256;
        float v = beta * dp[i] / (np[i]*kn + EPS);
        sc[t] = v; mx = fmaxf(mx, v);
    }
    mx = blk_max_(mx, sred);
    float ls = 0.f;
    #pragma unroll
    for (int t = 0; t < 16; t++){ sc[t] = __expf(sc[t]-mx); ls += sc[t]; }
    float tot = blk_sum_(ls, sred);
    float inv = 1.f / tot;
    #pragma unroll
    for (int t = 0; t < 16; t++){
        int i = threadIdx.x + t*256;
        swg[i] = gate*sc[t]*inv + (1.f-gate)*pw[i];
    }
    __syncthreads();
    float lp[16]; float ls2 = 0.f;
    #pragma unroll
    for (int t = 0; t < 16; t++){
        int i = threadIdx.x + t*256;
        float ws = s0*swg[(i+N-1)&(N-1)] + s1*swg[i] + s2*swg[(i+1)&(N-1)];
        float wp = __powf(ws, gam);
        lp[t] = wp; ls2 += wp;
    }
    float tot2 = blk_sum_(ls2, sred);
    float inv2 = 1.f / (tot2 + EPS);
    #pragma unroll
    for (int t = 0; t < 16; t++){
        int i = threadIdx.x + t*256;
        g_w[(size_t)hi*BN_ + (size_t)b*N + i] = lp[t]*inv2;
    }
}

// ---- PASS 0: read fp32 memory; write fp16 image; dots(k0,k1) + norms ----
__global__ void k_pass0(const float* __restrict__ mem){
    constexpr int CHUNK = 256, RPB = 16, ITERS = CHUNK/RPB;
    const int b   = blockIdx.y;
    const int n0  = blockIdx.x * CHUNK;
    const int tid = threadIdx.x;
    const int lane = tid & 15, rg = tid >> 4;

    __shared__ float4 skA[16], skB[16];
    if (tid < 16){
        skA[tid] = ((const float4*)(g_k + (size_t)0*B*M + b*M))[tid];
        skB[tid] = ((const float4*)(g_k + (size_t)1*B*M + b*M))[tid];
    }
    __syncthreads();

    const float4* mrow = (const float4*)mem + (size_t)b*N*(M/4);
    uint2* orow = (uint2*)g_mem16 + ((size_t)b*N)*(M/4);

    #pragma unroll 4
    for (int it = 0; it < ITERS; ++it){
        int n = n0 + it*RPB + rg;
        float4 m = mrow[(size_t)n*(M/4) + lane];
        __half2 ha = __floats2half2_rn(m.x, m.y);
        __half2 hb = __floats2half2_rn(m.z, m.w);
        uint2 st;
        st.x = *reinterpret_cast<const unsigned*>(&ha);
        st.y = *reinterpret_cast<const unsigned*>(&hb);
        orow[(size_t)n*(M/4) + lane] = st;

        size_t wi = (size_t)b*N + n;
        float4 kA = skA[lane], kB = skB[lane];
        float dA = m.x*kA.x + m.y*kA.y + m.z*kA.z + m.w*kA.w;
        float dB = m.x*kB.x + m.y*kB.y + m.z*kB.z + m.w*kB.w;
        float ss = m.x*m.x + m.y*m.y + m.z*m.z + m.w*m.w;
        #pragma unroll
        for (int o = 1; o < 16; o <<= 1){
            dA += __shfl_xor_sync(0xffffffffu, dA, o);
            dB += __shfl_xor_sync(0xffffffffu, dB, o);
            ss += __shfl_xor_sync(0xffffffffu, ss, o);
        }
        if (lane == 0){
            g_dot[wi]       = dA;
            g_dot[BN_ + wi] = dB;
            g_nrm[wi]       = sqrtf(ss);
        }
    }
}

// ---- PASSES 1..4: read fp16 image, recompute write chain, dots/reads ----
template<int PASS>
__global__ void k_pass16(){
    constexpr int NPRE  = PASS - 1;
    constexpr int NPOST = (PASS <= 3) ? 1 : 0;
    constexpr int NAPP  = NPRE + NPOST;
    constexpr int NDOT  = (PASS == 4) ? 0 : ((PASS == 3) ? 1 : 2);
    constexpr int RSLOT = NPRE;
    constexpr int RHEAD = 2*NPRE;
    constexpr int KB    = 2*PASS;

    const int b   = blockIdx.y;
    const int n0  = blockIdx.x * 256;
    const int tid = threadIdx.x;
    const int lane = tid & 7, rg = tid >> 3;

    __shared__ float sk[2][64];
    __shared__ float se[3][64], sa[3][64];
    if (tid < 64){
        if (NDOT >= 1) sk[0][tid] = g_k[(size_t)(KB  )*B*M + b*M + tid];
        if (NDOT >= 2) sk[1][tid] = g_k[(size_t)(KB+1)*B*M + b*M + tid];
        #pragma unroll
        for (int j = 0; j < NAPP; j++){
            se[j][tid] = g_e[(size_t)j*B*M + b*M + tid];
            sa[j][tid] = g_a[(size_t)j*B*M + b*M + tid];
        }
    }
    __syncthreads();

    float kr0[8], kr1[8], er[3][8], ar[3][8];
    #pragma unroll
    for (int t = 0; t < 8; t++){
        if (NDOT >= 1) kr0[t] = sk[0][lane*8+t];
        if (NDOT >= 2) kr1[t] = sk[1][lane*8+t];
        #pragma unroll
        for (int j = 0; j < NAPP; j++){ er[j][t] = se[j][lane*8+t]; ar[j][t] = sa[j][lane*8+t]; }
    }

    const uint4* base = (const uint4*)g_mem16 + ((size_t)b*N + n0)*8;
    float racc[8];
    #pragma unroll
    for (int t = 0; t < 8; t++) racc[t] = 0.f;

    #pragma unroll
    for (int it = 0; it < 8; ++it){
        int n = n0 + it*32 + rg;
        uint4 raw = base[(size_t)(it*32 + rg)*8 + lane];
        float f[8];
        {
            __half2 h0 = *reinterpret_cast<const __half2*>(&raw.x);
            __half2 h1 = *reinterpret_cast<const __half2*>(&raw.y);
            __half2 h2 = *reinterpret_cast<const __half2*>(&raw.z);
            __half2 h3 = *reinterpret_cast<const __half2*>(&raw.w);
            float2 a0 = __half22float2(h0), a1 = __half22float2(h1);
            float2 a2 = __half22float2(h2), a3 = __half22float2(h3);
            f[0]=a0.x; f[1]=a0.y; f[2]=a1.x; f[3]=a1.y;
            f[4]=a2.x; f[5]=a2.y; f[6]=a3.x; f[7]=a3.y;
        }
        size_t wi = (size_t)b*N + n;
        #pragma unroll
        for (int j = 0; j < NPRE; j++){
            float wv = g_w[(size_t)(2*j+1)*BN_ + wi];
            #pragma unroll
            for (int t = 0; t < 8; t++)
                f[t] = fmaf(wv, fmaf(-f[t], er[j][t], ar[j][t]), f[t]);
        }
        {
            float wr = g_w[(size_t)RHEAD*BN_ + wi];
            #pragma unroll
            for (int t = 0; t < 8; t++) racc[t] = fmaf(wr, f[t], racc[t]);
        }
        #pragma unroll
        for (int j = NPRE; j < NAPP; j++){
            float wv = g_w[(size_t)(2*j+1)*BN_ + wi];
            #pragma unroll
            for (int t = 0; t < 8; t++)
                f[t] = fmaf(wv, fmaf(-f[t], er[j][t], ar[j][t]), f[t]);
        }
        if (NDOT >= 1){
            float dA = 0.f, dB = 0.f, ss = 0.f;
            #pragma unroll
            for (int t = 0; t < 8; t++){
                dA = fmaf(f[t], kr0[t], dA);
                if (NDOT >= 2) dB = fmaf(f[t], kr1[t], dB);
                ss = fmaf(f[t], f[t], ss);
            }
            #pragma unroll
            for (int o = 1; o < 8; o <<= 1){
                dA += __shfl_xor_sync(0xffffffffu, dA, o);
                ss += __shfl_xor_sync(0xffffffffu, ss, o);
                if (NDOT >= 2) dB += __shfl_xor_sync(0xffffffffu, dB, o);
            }
            if (lane == 0){
                g_dot[wi] = dA;
                if (NDOT >= 2) g_dot[BN_ + wi] = dB;
                g_nrm[wi] = sqrtf(ss);
            }
        }
    }
    __shared__ float sr[32][64];
    #pragma unroll
    for (int t = 0; t < 8; t++) sr[rg][lane*8+t] = racc[t];
    __syncthreads();
    if (tid < 64){
        float s = 0.f;
        #pragma unroll
        for (int r = 0; r < 32; r++) s += sr[r][tid];
        atomicAdd(&g_reads[(size_t)RSLOT*B*M + b*M + tid], s);
    }
}

extern "C" void kernel_launch(void* const* d_in, const int* in_sizes, int n_in,
                              void* d_out, int out_size){
    const float* in_data = (const float*)d_in[0];
    const float* memory  = (const float*)d_in[1];
    const float* h0      = (const float*)d_in[2];
    const float* c0      = (const float*)d_in[3];
    const float* prevw   = (const float*)d_in[4];
    const float* prevr   = (const float*)d_in[5];
    const float* W_ih    = (const float*)d_in[6];
    const float* b_ih    = (const float*)d_in[7];
    const float* W_hh    = (const float*)d_in[8];
    const float* b_hh    = (const float*)d_in[9];
    const float* W_out   = (const float*)d_in[10];
    const float* b_out   = (const float*)d_in[11];
    const float* W_addr  = (const float*)d_in[12];
    const float* b_addr  = (const float*)d_in[13];
    const float* W_ea    = (const float*)d_in[14];
    const float* b_ea    = (const float*)d_in[15];
    float* out = (float*)d_out;

    // controller
    int prep_total = B*KL + 4*C*KL;
    k_prep<<<(prep_total + 255)/256, 256>>>(in_data, prevr, h0, W_ih, W_hh, b_ih, b_hh);
    k_gates<<<dim3(4*C/32, B/64), 256>>>(c0);
    k_proj<<<dim3((NPROJ+31)/32, B/64), 256>>>(W_addr, b_addr, W_ea, b_ea);
    k_head_params<<<dim3(B, 8), 64>>>();

    // memory passes with interleaved weight computations
    dim3 pg(N/256, B);
    k_pass0<<<pg, 256>>>(memory);
    k_weights<<<dim3(B,2), 256>>>(0, prevw);
    k_pass16<1><<<pg, 256>>>();
    k_weights<<<dim3(B,2), 256>>>(2, prevw);
    k_pass16<2><<<pg, 256>>>();
    k_weights<<<dim3(B,2), 256>>>(4, prevw);
    k_pass16<3><<<pg, 256>>>();
    k_weights<<<dim3(B,1), 256>>>(6, prevw);
    k_pass16<4><<<pg, 256>>>();

    // output
    k_out<<<B, 256>>>(W_out, b_out, out);
}

// round 7
// speedup vs baseline: 1.5463x; 1.2730x over previous
#include <cuda_runtime.h>
#include <cuda_fp16.h>
#include <math.h>

// ---- problem constants ----
constexpr int B   = 256;
constexpr int N   = 4096;
constexpr int M   = 64;
constexpr int C   = 512;
constexpr int H   = 4;
constexpr int INP = 64;
constexpr int OUTD= 64;
constexpr int XPART = INP + H*M;      // 320
constexpr int KL    = XPART + C;      // 832
constexpr int NADDR = 2*H*(M+6);      // 560
constexpr int NEA   = H*2*M;          // 512
constexpr int NPROJ = NADDR + NEA;    // 1072
constexpr int KOUT  = C + H*M;        // 768
constexpr int BN_   = B*N;            // 1048576
constexpr float EPS = 1e-8f;

// ---- scratch (device globals: allocation-free) ----
__device__ float  g_xcat [B*KL];
__device__ float  g_Wcat [4*C*KL];    // interleaved rows: 4*ci + gate
__device__ float  g_bcat [4*C];
__device__ float  g_hst  [B*C];
__device__ float  g_cst  [B*C];
__device__ float  g_P    [B*NPROJ];
__device__ float  g_k    [8*B*M];
__device__ float  g_knorm[8*B];
__device__ float  g_beta [8*B];
__device__ float  g_gate [8*B];
__device__ float  g_sv   [8*B*3];
__device__ float  g_gamma[8*B];
__device__ float  g_e    [4*B*M];
__device__ float  g_a    [4*B*M];
__device__ float  g_w    [7*BN_];
__device__ float  g_dot  [2*BN_];
__device__ float  g_nrm  [BN_];
__device__ float  g_reads[4*B*M];
__device__ __half g_mem16[(size_t)B*N*M];

__device__ __forceinline__ float sigmoidf_(float x){ return 1.f/(1.f+__expf(-x)); }
__device__ __forceinline__ float softplusf_(float x){ return x>20.f ? x : log1pf(__expf(x)); }

__device__ __forceinline__ void cp_async4(void* sdst, const void* gsrc){
    unsigned s = (unsigned)__cvta_generic_to_shared(sdst);
    asm volatile("cp.async.ca.shared.global [%0], [%1], 4;" :: "r"(s), "l"(gsrc));
}
__device__ __forceinline__ void cp_commit(){ asm volatile("cp.async.commit_group;"); }
template<int NG> __device__ __forceinline__ void cp_wait(){ asm volatile("cp.async.wait_group %0;" :: "n"(NG)); }

// ---- fused builder: xcat + interleaved Wcat + bcat ----
__global__ void k_prep(const float* __restrict__ ind, const float* __restrict__ prd,
                       const float* __restrict__ h0,
                       const float* __restrict__ W_ih, const float* __restrict__ W_hh,
                       const float* __restrict__ b_ih, const float* __restrict__ b_hh){
    int idx = blockIdx.x*blockDim.x + threadIdx.x;
    if (idx < B*KL){
        int b = idx / KL, j = idx % KL;
        float v;
        if (j < INP)            v = ind[b*INP + j];
        else if (j < XPART) {   int r = j - INP; v = prd[(r/M)*B*M + b*M + (r%M)]; }
        else                    v = h0[b*C + (j - XPART)];
        g_xcat[idx] = v;
    }
    int idx2 = idx - B*KL;
    if (idx2 >= 0 && idx2 < 4*C*KL){
        int j = idx2 / KL, kk = idx2 % KL;
        int ci = j >> 2, gg = j & 3;
        int src = gg*C + ci;
        g_Wcat[idx2] = (kk < XPART) ? W_ih[(size_t)src*XPART + kk] : W_hh[(size_t)src*C + (kk - XPART)];
        if (kk == 0) g_bcat[j] = b_ih[src] + b_hh[src];
    }
}

// ============ pipelined GEMM: gates + fused LSTM epilogue ============
__global__ void k_gates(const float* __restrict__ c0){
    constexpr int K = KL, NK = K/16;
    __shared__ float As[2][64][17];
    __shared__ float Ws[2][32][17];
    const int tid = threadIdx.x;
    const int tx = tid & 7, ty = tid >> 3;
    const int bn = blockIdx.x*32, bm = blockIdx.y*64;
    const float* A = g_xcat;
    const float* W = g_Wcat;

    auto prefetch = [&](int kb, int buf){
        int k0 = kb*16;
        #pragma unroll
        for (int r = 0; r < 4; r++){
            int idx = tid + r*256;
            int i = idx >> 4, k = idx & 15;
            cp_async4(&As[buf][i][k], &A[(size_t)(bm+i)*K + k0 + k]);
        }
        #pragma unroll
        for (int r = 0; r < 2; r++){
            int idx = tid + r*256;
            int i = idx >> 4, k = idx & 15;
            cp_async4(&Ws[buf][i][k], &W[(size_t)(bn+i)*K + k0 + k]);
        }
    };

    float acc[2][4] = {};
    prefetch(0, 0); cp_commit();
    for (int kb = 0; kb < NK; kb++){
        int cur = kb & 1;
        if (kb+1 < NK){ prefetch(kb+1, cur^1); cp_commit(); cp_wait<1>(); }
        else cp_wait<0>();
        __syncthreads();
        #pragma unroll
        for (int k = 0; k < 16; k++){
            float av0 = As[cur][ty*2+0][k], av1 = As[cur][ty*2+1][k];
            float wv[4];
            #pragma unroll
            for (int j = 0; j < 4; j++) wv[j] = Ws[cur][tx*4+j][k];
            #pragma unroll
            for (int j = 0; j < 4; j++){ acc[0][j] += av0*wv[j]; acc[1][j] += av1*wv[j]; }
        }
        __syncthreads();
    }
    int ci = (bn >> 2) + tx;
    #pragma unroll
    for (int i = 0; i < 2; i++){
        int m = bm + ty*2 + i;
        float ig = acc[i][0] + g_bcat[bn + tx*4 + 0];
        float fg = acc[i][1] + g_bcat[bn + tx*4 + 1];
        float gg = acc[i][2] + g_bcat[bn + tx*4 + 2];
        float og = acc[i][3] + g_bcat[bn + tx*4 + 3];
        float cn = sigmoidf_(fg)*c0[(size_t)m*C + ci] + sigmoidf_(ig)*tanhf(gg);
        g_cst[(size_t)m*C + ci] = cn;
        g_hst[(size_t)m*C + ci] = sigmoidf_(og)*tanhf(cn);
    }
}

// ============ pipelined GEMM: fused addr+ea projections ============
__global__ void k_proj(const float* __restrict__ W1, const float* __restrict__ b1,
                       const float* __restrict__ W2, const float* __restrict__ b2){
    constexpr int K = C, NK = K/16, No = NPROJ;
    __shared__ float As[2][64][17];
    __shared__ float Ws[2][32][17];
    const int tid = threadIdx.x;
    const int tx = tid & 7, ty = tid >> 3;
    const int bn = blockIdx.x*32, bm = blockIdx.y*64;
    const float* A = g_cst;

    auto prefetch = [&](int kb, int buf){
        int k0 = kb*16;
        #pragma unroll
        for (int r = 0; r < 4; r++){
            int idx = tid + r*256;
            int i = idx >> 4, k = idx & 15;
            cp_async4(&As[buf][i][k], &A[(size_t)(bm+i)*K + k0 + k]);
        }
        #pragma unroll
        for (int r = 0; r < 2; r++){
            int idx = tid + r*256;
            int i = idx >> 4, k = idx & 15;
            int j = bn + i; if (j > No-1) j = No-1;
            const float* src = (j < NADDR) ? &W1[(size_t)j*K + k0 + k]
                                           : &W2[(size_t)(j-NADDR)*K + k0 + k];
            cp_async4(&Ws[buf][i][k], src);
        }
    };

    float acc[2][4] = {};
    prefetch(0, 0); cp_commit();
    for (int kb = 0; kb < NK; kb++){
        int cur = kb & 1;
        if (kb+1 < NK){ prefetch(kb+1, cur^1); cp_commit(); cp_wait<1>(); }
        else cp_wait<0>();
        __syncthreads();
        #pragma unroll
        for (int k = 0; k < 16; k++){
            float av0 = As[cur][ty*2+0][k], av1 = As[cur][ty*2+1][k];
            float wv[4];
            #pragma unroll
            for (int j = 0; j < 4; j++) wv[j] = Ws[cur][tx*4+j][k];
            #pragma unroll
            for (int j = 0; j < 4; j++){ acc[0][j] += av0*wv[j]; acc[1][j] += av1*wv[j]; }
        }
        __syncthreads();
    }
    #pragma unroll
    for (int i = 0; i < 2; i++){
        int m = bm + ty*2 + i;
        #pragma unroll
        for (int j = 0; j < 4; j++){
            int n = bn + tx*4 + j;
            if (n < No){
                float bb = (n < NADDR) ? b1[n] : b2[n - NADDR];
                g_P[(size_t)m*No + n] = acc[i][j] + bb;
            }
        }
    }
}

// ============ output layer ============
__global__ void k_out(const float* __restrict__ W, const float* __restrict__ bias,
                      float* __restrict__ out){
    const int m = blockIdx.x;
    const int tid = threadIdx.x, lane = tid & 31, wid = tid >> 5;
    __shared__ float sA[KOUT];
    for (int idx = tid; idx < KOUT; idx += 256){
        float v;
        if (idx < C) v = g_hst[(size_t)m*C + idx];
        else { int r = idx - C; v = g_reads[(size_t)(r>>6)*B*M + m*M + (r&63)]; }
        sA[idx] = v;
    }
    __syncthreads();
    #pragma unroll
    for (int nn = 0; nn < 8; nn++){
        int n = wid*8 + nn;
        const float* wr = &W[(size_t)n*KOUT];
        float s = 0.f;
        #pragma unroll 6
        for (int kk = lane; kk < KOUT; kk += 32) s += sA[kk]*wr[kk];
        #pragma unroll
        for (int o = 16; o; o >>= 1) s += __shfl_xor_sync(0xffffffffu, s, o);
        if (lane == 0) out[(size_t)m*OUTD + n] = sigmoidf_(s + bias[n]);
    }
}

// ---- per-head addressing params ----
__global__ void k_head_params(){
    int b = blockIdx.x, hi = blockIdx.y, t = threadIdx.x;
    const float* pa = g_P + (size_t)b*NPROJ + hi*70;
    float kv = tanhf(pa[t]);
    g_k[(size_t)(hi*B + b)*M + t] = kv;
    float sq = kv*kv;
    #pragma unroll
    for (int o = 16; o; o >>= 1) sq += __shfl_xor_sync(0xffffffffu, sq, o);
    __shared__ float sh[2];
    if ((t & 31) == 0) sh[t >> 5] = sq;
    __syncthreads();
    if (t == 0){
        g_knorm[hi*B + b] = sqrtf(sh[0] + sh[1]);
        g_beta [hi*B + b] = softplusf_(pa[64]);
        g_gate [hi*B + b] = sigmoidf_(pa[65]);
        float p0 = pa[66], p1 = pa[67], p2 = pa[68];
        float mx = fmaxf(p0, fmaxf(p1, p2));
        float e0 = __expf(p0-mx), e1 = __expf(p1-mx), e2 = __expf(p2-mx);
        float ssum = e0 + e1 + e2;
        g_sv[(hi*B+b)*3+0] = e0/ssum;
        g_sv[(hi*B+b)*3+1] = e1/ssum;
        g_sv[(hi*B+b)*3+2] = e2/ssum;
        g_gamma[hi*B + b] = 1.f + softplusf_(pa[69]);
    }
    if (hi & 1){
        int j = hi >> 1;
        const float* pe = g_P + (size_t)b*NPROJ + NADDR + j*128;
        g_e[(size_t)j*B*M + b*M + t] = sigmoidf_(pe[t]);
        g_a[(size_t)j*B*M + b*M + t] = tanhf(pe[64+t]);
    }
    if (hi < 4) g_reads[(size_t)hi*B*M + b*M + t] = 0.f;
}

// ---- block reduction helpers (256 threads) ----
__device__ __forceinline__ float blk_max_(float v, float* sh){
    #pragma unroll
    for (int o = 16; o; o >>= 1) v = fmaxf(v, __shfl_xor_sync(0xffffffffu, v, o));
    int w = threadIdx.x >> 5;
    if ((threadIdx.x & 31) == 0) sh[w] = v;
    __syncthreads();
    if (threadIdx.x < 8){
        v = sh[threadIdx.x];
        #pragma unroll
        for (int o = 4; o; o >>= 1) v = fmaxf(v, __shfl_xor_sync(0xffu, v, o));
        if (threadIdx.x == 0) sh[0] = v;
    }
    __syncthreads();
    v = sh[0];
    __syncthreads();
    return v;
}
__device__ __forceinline__ float blk_sum_(float v, float* sh){
    #pragma unroll
    for (int o = 16; o; o >>= 1) v += __shfl_xor_sync(0xffffffffu, v, o);
    int w = threadIdx.x >> 5;
    if ((threadIdx.x & 31) == 0) sh[w] = v;
    __syncthreads();
    if (threadIdx.x < 8){
        v = sh[threadIdx.x];
        #pragma unroll
        for (int o = 4; o; o >>= 1) v += __shfl_xor_sync(0xffu, v, o);
        if (threadIdx.x == 0) sh[0] = v;
    }
    __syncthreads();
    v = sh[0];
    __syncthreads();
    return v;
}

// ---- addressing weights ----
__global__ void k_weights(int hibase, const float* __restrict__ prevw){
    int b = blockIdx.x;
    int hi = hibase + blockIdx.y;
    int slot = blockIdx.y;
    __shared__ float swg[N];
    __shared__ float sred[8];
    const float* dp = g_dot + (size_t)slot*BN_ + (size_t)b*N;
    const float* np = g_nrm + (size_t)b*N;
    const float* pw = prevw + (size_t)hi*BN_ + (size_t)b*N;
    float beta = g_beta[hi*B+b], gate = g_gate[hi*B+b];
    float kn = g_knorm[hi*B+b],  gam  = g_gamma[hi*B+b];
    float s0 = g_sv[(hi*B+b)*3+0], s1 = g_sv[(hi*B+b)*3+1], s2 = g_sv[(hi*B+b)*3+2];

    float sc[16];
    float mx = -1e30f;
    #pragma unroll
    for (int t = 0; t < 16; t++){
        int i = threadIdx.x + t*256;
        float v = beta * dp[i] / (np[i]*kn + EPS);
        sc[t] = v; mx = fmaxf(mx, v);
    }
    mx = blk_max_(mx, sred);
    float ls = 0.f;
    #pragma unroll
    for (int t = 0; t < 16; t++){ sc[t] = __expf(sc[t]-mx); ls += sc[t]; }
    float tot = blk_sum_(ls, sred);
    float inv = 1.f / tot;
    #pragma unroll
    for (int t = 0; t < 16; t++){
        int i = threadIdx.x + t*256;
        swg[i] = gate*sc[t]*inv + (1.f-gate)*pw[i];
    }
    __syncthreads();
    float lp[16]; float ls2 = 0.f;
    #pragma unroll
    for (int t = 0; t < 16; t++){
        int i = threadIdx.x + t*256;
        float ws = s0*swg[(i+N-1)&(N-1)] + s1*swg[i] + s2*swg[(i+1)&(N-1)];
        float wp = __powf(ws, gam);
        lp[t] = wp; ls2 += wp;
    }
    float tot2 = blk_sum_(ls2, sred);
    float inv2 = 1.f / (tot2 + EPS);
    #pragma unroll
    for (int t = 0; t < 16; t++){
        int i = threadIdx.x + t*256;
        g_w[(size_t)hi*BN_ + (size_t)b*N + i] = lp[t]*inv2;
    }
}

// ---- PASS 0: read fp32 memory; write fp16 image; dots(k0,k1) + norms ----
// MLP=4 batched loads. Forward traversal.
__global__ void k_pass0(const float* __restrict__ mem){
    const int b   = blockIdx.y;
    const int n0  = blockIdx.x * 256;
    const int tid = threadIdx.x;
    const int lane = tid & 15, rg = tid >> 4;   // 16 rows/step

    __shared__ float4 skA[16], skB[16];
    if (tid < 16){
        skA[tid] = ((const float4*)(g_k + (size_t)0*B*M + b*M))[tid];
        skB[tid] = ((const float4*)(g_k + (size_t)1*B*M + b*M))[tid];
    }
    __syncthreads();
    const float4 kA = skA[lane], kB = skB[lane];

    const float4* mrow = (const float4*)mem + (size_t)b*N*(M/4);
    uint2* orow = (uint2*)g_mem16 + ((size_t)b*N)*(M/4);

    #pragma unroll
    for (int bt = 0; bt < 4; ++bt){
        float4 mv[4]; int ln[4];
        #pragma unroll
        for (int t = 0; t < 4; t++){
            ln[t] = n0 + bt*64 + t*16 + rg;
            mv[t] = mrow[(size_t)ln[t]*(M/4) + lane];
        }
        #pragma unroll
        for (int t = 0; t < 4; t++){
            float4 m = mv[t];
            __half2 ha = __floats2half2_rn(m.x, m.y);
            __half2 hb = __floats2half2_rn(m.z, m.w);
            uint2 st;
            st.x = *reinterpret_cast<const unsigned*>(&ha);
            st.y = *reinterpret_cast<const unsigned*>(&hb);
            orow[(size_t)ln[t]*(M/4) + lane] = st;

            size_t wi = (size_t)b*N + ln[t];
            float dA = m.x*kA.x + m.y*kA.y + m.z*kA.z + m.w*kA.w;
            float dB = m.x*kB.x + m.y*kB.y + m.z*kB.z + m.w*kB.w;
            float ss = m.x*m.x + m.y*m.y + m.z*m.z + m.w*m.w;
            #pragma unroll
            for (int o = 1; o < 16; o <<= 1){
                dA += __shfl_xor_sync(0xffffffffu, dA, o);
                dB += __shfl_xor_sync(0xffffffffu, dB, o);
                ss += __shfl_xor_sync(0xffffffffu, ss, o);
            }
            if (lane == 0){
                g_dot[wi]       = dA;
                g_dot[BN_ + wi] = dB;
                g_nrm[wi]       = sqrtf(ss);
            }
        }
    }
}

// ---- PASSES 1..4: fp16 image; 16 lanes/row (uint2); MLP=4; serpentine ----
template<int PASS, bool REV>
__global__ void k_pass16(){
    constexpr int NPRE  = PASS - 1;
    constexpr int NPOST = (PASS <= 3) ? 1 : 0;
    constexpr int NAPP  = NPRE + NPOST;
    constexpr int NDOT  = (PASS == 4) ? 0 : ((PASS == 3) ? 1 : 2);
    constexpr int RSLOT = NPRE;
    constexpr int RHEAD = 2*NPRE;
    constexpr int KB    = 2*PASS;

    const int bx = REV ? (int)(gridDim.x - 1 - blockIdx.x) : (int)blockIdx.x;
    const int b  = REV ? (int)(gridDim.y - 1 - blockIdx.y) : (int)blockIdx.y;
    const int n0 = bx * 256;
    const int tid = threadIdx.x;
    const int lane = tid & 15, rg = tid >> 4;   // 16 rows/step, 4 half-elems/lane

    __shared__ float sk[2][64], se[3][64], sa[3][64];
    if (tid < 64){
        if (NDOT >= 1) sk[0][tid] = g_k[(size_t)(KB  )*B*M + b*M + tid];
        if (NDOT >= 2) sk[1][tid] = g_k[(size_t)(KB+1)*B*M + b*M + tid];
        #pragma unroll
        for (int j = 0; j < NAPP; j++){
            se[j][tid] = g_e[(size_t)j*B*M + b*M + tid];
            sa[j][tid] = g_a[(size_t)j*B*M + b*M + tid];
        }
    }
    __syncthreads();

    float kr0[4], kr1[4], er[3][4], ar[3][4];
    #pragma unroll
    for (int t = 0; t < 4; t++){
        int ix = lane*4 + t;
        if (NDOT >= 1) kr0[t] = sk[0][ix];
        if (NDOT >= 2) kr1[t] = sk[1][ix];
        #pragma unroll
        for (int j = 0; j < NAPP; j++){ er[j][t] = se[j][ix]; ar[j][t] = sa[j][ix]; }
    }

    const uint2* base = (const uint2*)g_mem16 + ((size_t)b*N + n0)*(M/4);
    float racc[4] = {0.f, 0.f, 0.f, 0.f};

    #pragma unroll
    for (int bt = 0; bt < 4; ++bt){
        uint2 raw[4]; int ln[4];
        float wpre[4][3], wr[4], wpost[4];
        #pragma unroll
        for (int t = 0; t < 4; t++){
            ln[t] = bt*64 + t*16 + rg;
            raw[t] = base[(size_t)ln[t]*(M/4) + lane];
            size_t wi = (size_t)b*N + n0 + ln[t];
            #pragma unroll
            for (int j = 0; j < NPRE; j++) wpre[t][j] = g_w[(size_t)(2*j+1)*BN_ + wi];
            wr[t] = g_w[(size_t)RHEAD*BN_ + wi];
            if (NPOST) wpost[t] = g_w[(size_t)(2*NPRE+1)*BN_ + wi];
        }
        #pragma unroll
        for (int t = 0; t < 4; t++){
            float f[4];
            {
                __half2 h0 = *reinterpret_cast<const __half2*>(&raw[t].x);
                __half2 h1 = *reinterpret_cast<const __half2*>(&raw[t].y);
                float2 a0 = __half22float2(h0), a1 = __half22float2(h1);
                f[0]=a0.x; f[1]=a0.y; f[2]=a1.x; f[3]=a1.y;
            }
            #pragma unroll
            for (int j = 0; j < NPRE; j++){
                float wv = wpre[t][j];
                #pragma unroll
                for (int q = 0; q < 4; q++)
                    f[q] = fmaf(wv, fmaf(-f[q], er[j][q], ar[j][q]), f[q]);
            }
            #pragma unroll
            for (int q = 0; q < 4; q++) racc[q] = fmaf(wr[t], f[q], racc[q]);
            if (NPOST){
                float wv = wpost[t];
                #pragma unroll
                for (int q = 0; q < 4; q++)
                    f[q] = fmaf(wv, fmaf(-f[q], er[NPRE][q], ar[NPRE][q]), f[q]);
            }
            if (NDOT >= 1){
                float dA = 0.f, dB = 0.f, ss = 0.f;
                #pragma unroll
                for (int q = 0; q < 4; q++){
                    dA = fmaf(f[q], kr0[q], dA);
                    if (NDOT >= 2) dB = fmaf(f[q], kr1[q], dB);
                    ss = fmaf(f[q], f[q], ss);
                }
                #pragma unroll
                for (int o = 1; o < 16; o <<= 1){
                    dA += __shfl_xor_sync(0xffffffffu, dA, o);
                    ss += __shfl_xor_sync(0xffffffffu, ss, o);
                    if (NDOT >= 2) dB += __shfl_xor_sync(0xffffffffu, dB, o);
                }
                if (lane == 0){
                    size_t wi = (size_t)b*N + n0 + ln[t];
                    g_dot[wi] = dA;
                    if (NDOT >= 2) g_dot[BN_ + wi] = dB;
                    g_nrm[wi] = sqrtf(ss);
                }
            }
        }
    }
    // block-level read reduction: sr[rowgroup][64]
    __shared__ float sr[16][64];
    #pragma unroll
    for (int q = 0; q < 4; q++) sr[rg][lane*4+q] = racc[q];
    __syncthreads();
    if (tid < 64){
        float s = 0.f;
        #pragma unroll
        for (int r = 0; r < 16; r++) s += sr[r][tid];
        atomicAdd(&g_reads[(size_t)RSLOT*B*M + b*M + tid], s);
    }
}

extern "C" void kernel_launch(void* const* d_in, const int* in_sizes, int n_in,
                              void* d_out, int out_size){
    const float* in_data = (const float*)d_in[0];
    const float* memory  = (const float*)d_in[1];
    const float* h0      = (const float*)d_in[2];
    const float* c0      = (const float*)d_in[3];
    const float* prevw   = (const float*)d_in[4];
    const float* prevr   = (const float*)d_in[5];
    const float* W_ih    = (const float*)d_in[6];
    const float* b_ih    = (const float*)d_in[7];
    const float* W_hh    = (const float*)d_in[8];
    const float* b_hh    = (const float*)d_in[9];
    const float* W_out   = (const float*)d_in[10];
    const float* b_out   = (const float*)d_in[11];
    const float* W_addr  = (const float*)d_in[12];
    const float* b_addr  = (const float*)d_in[13];
    const float* W_ea    = (const float*)d_in[14];
    const float* b_ea    = (const float*)d_in[15];
    float* out = (float*)d_out;

    // controller
    int prep_total = B*KL + 4*C*KL;
    k_prep<<<(prep_total + 255)/256, 256>>>(in_data, prevr, h0, W_ih, W_hh, b_ih, b_hh);
    k_gates<<<dim3(4*C/32, B/64), 256>>>(c0);
    k_proj<<<dim3((NPROJ+31)/32, B/64), 256>>>(W_addr, b_addr, W_ea, b_ea);
    k_head_params<<<dim3(B, 8), 64>>>();

    // memory passes (serpentine traversal for L2 reuse)
    dim3 pg(N/256, B);
    k_pass0<<<pg, 256>>>(memory);
    k_weights<<<dim3(B,2), 256>>>(0, prevw);
    k_pass16<1, true ><<<pg, 256>>>();
    k_weights<<<dim3(B,2), 256>>>(2, prevw);
    k_pass16<2, false><<<pg, 256>>>();
    k_weights<<<dim3(B,2), 256>>>(4, prevw);
    k_pass16<3, true ><<<pg, 256>>>();
    k_weights<<<dim3(B,1), 256>>>(6, prevw);
    k_pass16<4, false><<<pg, 256>>>();

    // output
    k_out<<<B, 256>>>(W_out, b_out, out);
}

// round 10
// speedup vs baseline: 1.6207x; 1.0481x over previous
#include <cuda_runtime.h>
#include <cuda_fp16.h>
#include <math.h>

// ---- problem constants ----
constexpr int B   = 256;
constexpr int N   = 4096;
constexpr int M   = 64;
constexpr int C   = 512;
constexpr int H   = 4;
constexpr int INP = 64;
constexpr int OUTD= 64;
constexpr int XPART = INP + H*M;      // 320
constexpr int KL    = XPART + C;      // 832
constexpr int NADDR = 2*H*(M+6);      // 560
constexpr int NEA   = H*2*M;          // 512
constexpr int NPROJ = NADDR + NEA;    // 1072
constexpr int KOUT  = C + H*M;        // 768
constexpr int BN_   = B*N;            // 1048576
constexpr float EPS = 1e-8f;

// ---- scratch (device globals: allocation-free) ----
__device__ float  g_xcat [B*KL];
__device__ float  g_Wcat [4*C*KL];    // interleaved rows: 4*ci + gate
__device__ float  g_bcat [4*C];
__device__ float  g_hst  [B*C];
__device__ float  g_cst  [B*C];
__device__ float  g_P    [B*NPROJ];
__device__ float  g_k    [8*B*M];
__device__ float  g_knorm[8*B];
__device__ float  g_beta [8*B];
__device__ float  g_gate [8*B];
__device__ float  g_sv   [8*B*3];
__device__ float  g_gamma[8*B];
__device__ float  g_e    [4*B*M];
__device__ float  g_a    [4*B*M];
__device__ float  g_w    [7*BN_];
__device__ float  g_dot  [2*BN_];
__device__ float  g_nrm  [BN_];
__device__ float  g_reads[4*B*M];
__device__ __half g_mem16[(size_t)B*N*M];

__device__ __forceinline__ float sigmoidf_(float x){ return 1.f/(1.f+__expf(-x)); }
__device__ __forceinline__ float softplusf_(float x){ return x>20.f ? x : log1pf(__expf(x)); }

__device__ __forceinline__ void cp_async4(void* sdst, const void* gsrc){
    unsigned s = (unsigned)__cvta_generic_to_shared(sdst);
    asm volatile("cp.async.ca.shared.global [%0], [%1], 4;" :: "r"(s), "l"(gsrc));
}
__device__ __forceinline__ void cp_commit(){ asm volatile("cp.async.commit_group;"); }
template<int NG> __device__ __forceinline__ void cp_wait(){ asm volatile("cp.async.wait_group %0;" :: "n"(NG)); }

// ---- fused builder: xcat + interleaved Wcat + bcat ----
__global__ void k_prep(const float* __restrict__ ind, const float* __restrict__ prd,
                       const float* __restrict__ h0,
                       const float* __restrict__ W_ih, const float* __restrict__ W_hh,
                       const float* __restrict__ b_ih, const float* __restrict__ b_hh){
    int idx = blockIdx.x*blockDim.x + threadIdx.x;
    if (idx < B*KL){
        int b = idx / KL, j = idx % KL;
        float v;
        if (j < INP)            v = ind[b*INP + j];
        else if (j < XPART) {   int r = j - INP; v = prd[(r/M)*B*M + b*M + (r%M)]; }
        else                    v = h0[b*C + (j - XPART)];
        g_xcat[idx] = v;
    }
    int idx2 = idx - B*KL;
    if (idx2 >= 0 && idx2 < 4*C*KL){
        int j = idx2 / KL, kk = idx2 % KL;
        int ci = j >> 2, gg = j & 3;
        int src = gg*C + ci;
        g_Wcat[idx2] = (kk < XPART) ? W_ih[(size_t)src*XPART + kk] : W_hh[(size_t)src*C + (kk - XPART)];
        if (kk == 0) g_bcat[j] = b_ih[src] + b_hh[src];
    }
}

// ============ pipelined GEMM: gates + fused LSTM epilogue ============
__global__ void k_gates(const float* __restrict__ c0){
    constexpr int K = KL, NK = K/16;
    __shared__ float As[2][64][17];
    __shared__ float Ws[2][32][17];
    const int tid = threadIdx.x;
    const int tx = tid & 7, ty = tid >> 3;
    const int bn = blockIdx.x*32, bm = blockIdx.y*64;
    const float* A = g_xcat;
    const float* W = g_Wcat;

    auto prefetch = [&](int kb, int buf){
        int k0 = kb*16;
        #pragma unroll
        for (int r = 0; r < 4; r++){
            int idx = tid + r*256;
            int i = idx >> 4, k = idx & 15;
            cp_async4(&As[buf][i][k], &A[(size_t)(bm+i)*K + k0 + k]);
        }
        #pragma unroll
        for (int r = 0; r < 2; r++){
            int idx = tid + r*256;
            int i = idx >> 4, k = idx & 15;
            cp_async4(&Ws[buf][i][k], &W[(size_t)(bn+i)*K + k0 + k]);
        }
    };

    float acc[2][4] = {};
    prefetch(0, 0); cp_commit();
    for (int kb = 0; kb < NK; kb++){
        int cur = kb & 1;
        if (kb+1 < NK){ prefetch(kb+1, cur^1); cp_commit(); cp_wait<1>(); }
        else cp_wait<0>();
        __syncthreads();
        #pragma unroll
        for (int k = 0; k < 16; k++){
            float av0 = As[cur][ty*2+0][k], av1 = As[cur][ty*2+1][k];
            float wv[4];
            #pragma unroll
            for (int j = 0; j < 4; j++) wv[j] = Ws[cur][tx*4+j][k];
            #pragma unroll
            for (int j = 0; j < 4; j++){ acc[0][j] += av0*wv[j]; acc[1][j] += av1*wv[j]; }
        }
        __syncthreads();
    }
    int ci = (bn >> 2) + tx;
    #pragma unroll
    for (int i = 0; i < 2; i++){
        int m = bm + ty*2 + i;
        float ig = acc[i][0] + g_bcat[bn + tx*4 + 0];
        float fg = acc[i][1] + g_bcat[bn + tx*4 + 1];
        float gg = acc[i][2] + g_bcat[bn + tx*4 + 2];
        float og = acc[i][3] + g_bcat[bn + tx*4 + 3];
        float cn = sigmoidf_(fg)*c0[(size_t)m*C + ci] + sigmoidf_(ig)*tanhf(gg);
        g_cst[(size_t)m*C + ci] = cn;
        g_hst[(size_t)m*C + ci] = sigmoidf_(og)*tanhf(cn);
    }
}

// ============ pipelined GEMM: fused addr+ea projections ============
__global__ void k_proj(const float* __restrict__ W1, const float* __restrict__ b1,
                       const float* __restrict__ W2, const float* __restrict__ b2){
    constexpr int K = C, NK = K/16, No = NPROJ;
    __shared__ float As[2][64][17];
    __shared__ float Ws[2][32][17];
    const int tid = threadIdx.x;
    const int tx = tid & 7, ty = tid >> 3;
    const int bn = blockIdx.x*32, bm = blockIdx.y*64;
    const float* A = g_cst;

    auto prefetch = [&](int kb, int buf){
        int k0 = kb*16;
        #pragma unroll
        for (int r = 0; r < 4; r++){
            int idx = tid + r*256;
            int i = idx >> 4, k = idx & 15;
            cp_async4(&As[buf][i][k], &A[(size_t)(bm+i)*K + k0 + k]);
        }
        #pragma unroll
        for (int r = 0; r < 2; r++){
            int idx = tid + r*256;
            int i = idx >> 4, k = idx & 15;
            int j = bn + i; if (j > No-1) j = No-1;
            const float* src = (j < NADDR) ? &W1[(size_t)j*K + k0 + k]
                                           : &W2[(size_t)(j-NADDR)*K + k0 + k];
            cp_async4(&Ws[buf][i][k], src);
        }
    };

    float acc[2][4] = {};
    prefetch(0, 0); cp_commit();
    for (int kb = 0; kb < NK; kb++){
        int cur = kb & 1;
        if (kb+1 < NK){ prefetch(kb+1, cur^1); cp_commit(); cp_wait<1>(); }
        else cp_wait<0>();
        __syncthreads();
        #pragma unroll
        for (int k = 0; k < 16; k++){
            float av0 = As[cur][ty*2+0][k], av1 = As[cur][ty*2+1][k];
            float wv[4];
            #pragma unroll
            for (int j = 0; j < 4; j++) wv[j] = Ws[cur][tx*4+j][k];
            #pragma unroll
            for (int j = 0; j < 4; j++){ acc[0][j] += av0*wv[j]; acc[1][j] += av1*wv[j]; }
        }
        __syncthreads();
    }
    #pragma unroll
    for (int i = 0; i < 2; i++){
        int m = bm + ty*2 + i;
        #pragma unroll
        for (int j = 0; j < 4; j++){
            int n = bn + tx*4 + j;
            if (n < No){
                float bb = (n < NADDR) ? b1[n] : b2[n - NADDR];
                g_P[(size_t)m*No + n] = acc[i][j] + bb;
            }
        }
    }
}

// ============ output layer ============
__global__ void k_out(const float* __restrict__ W, const float* __restrict__ bias,
                      float* __restrict__ out){
    const int m = blockIdx.x;
    const int tid = threadIdx.x, lane = tid & 31, wid = tid >> 5;
    __shared__ float sA[KOUT];
    for (int idx = tid; idx < KOUT; idx += 256){
        float v;
        if (idx < C) v = g_hst[(size_t)m*C + idx];
        else { int r = idx - C; v = g_reads[(size_t)(r>>6)*B*M + m*M + (r&63)]; }
        sA[idx] = v;
    }
    __syncthreads();
    #pragma unroll
    for (int nn = 0; nn < 8; nn++){
        int n = wid*8 + nn;
        const float* wr = &W[(size_t)n*KOUT];
        float s = 0.f;
        #pragma unroll 6
        for (int kk = lane; kk < KOUT; kk += 32) s += sA[kk]*wr[kk];
        #pragma unroll
        for (int o = 16; o; o >>= 1) s += __shfl_xor_sync(0xffffffffu, s, o);
        if (lane == 0) out[(size_t)m*OUTD + n] = sigmoidf_(s + bias[n]);
    }
}

// ---- per-head addressing params ----
__global__ void k_head_params(){
    int b = blockIdx.x, hi = blockIdx.y, t = threadIdx.x;
    const float* pa = g_P + (size_t)b*NPROJ + hi*70;
    float kv = tanhf(pa[t]);
    g_k[(size_t)(hi*B + b)*M + t] = kv;
    float sq = kv*kv;
    #pragma unroll
    for (int o = 16; o; o >>= 1) sq += __shfl_xor_sync(0xffffffffu, sq, o);
    __shared__ float sh[2];
    if ((t & 31) == 0) sh[t >> 5] = sq;
    __syncthreads();
    if (t == 0){
        g_knorm[hi*B + b] = sqrtf(sh[0] + sh[1]);
        g_beta [hi*B + b] = softplusf_(pa[64]);
        g_gate [hi*B + b] = sigmoidf_(pa[65]);
        float p0 = pa[66], p1 = pa[67], p2 = pa[68];
        float mx = fmaxf(p0, fmaxf(p1, p2));
        float e0 = __expf(p0-mx), e1 = __expf(p1-mx), e2 = __expf(p2-mx);
        float ssum = e0 + e1 + e2;
        g_sv[(hi*B+b)*3+0] = e0/ssum;
        g_sv[(hi*B+b)*3+1] = e1/ssum;
        g_sv[(hi*B+b)*3+2] = e2/ssum;
        g_gamma[hi*B + b] = 1.f + softplusf_(pa[69]);
    }
    if (hi & 1){
        int j = hi >> 1;
        const float* pe = g_P + (size_t)b*NPROJ + NADDR + j*128;
        g_e[(size_t)j*B*M + b*M + t] = sigmoidf_(pe[t]);
        g_a[(size_t)j*B*M + b*M + t] = tanhf(pe[64+t]);
    }
    if (hi < 4) g_reads[(size_t)hi*B*M + b*M + t] = 0.f;
}

// ---- block reduction helpers (256 threads) ----
__device__ __forceinline__ float blk_max_(float v, float* sh){
    #pragma unroll
    for (int o = 16; o; o >>= 1) v = fmaxf(v, __shfl_xor_sync(0xffffffffu, v, o));
    int w = threadIdx.x >> 5;
    if ((threadIdx.x & 31) == 0) sh[w] = v;
    __syncthreads();
    if (threadIdx.x < 8){
        v = sh[threadIdx.x];
        #pragma unroll
        for (int o = 4; o; o >>= 1) v = fmaxf(v, __shfl_xor_sync(0xffu, v, o));
        if (threadIdx.x == 0) sh[0] = v;
    }
    __syncthreads();
    v = sh[0];
    __syncthreads();
    return v;
}
__device__ __forceinline__ float blk_sum_(float v, float* sh){
    #pragma unroll
    for (int o = 16; o; o >>= 1) v += __shfl_xor_sync(0xffffffffu, v, o);
    int w = threadIdx.x >> 5;
    if ((threadIdx.x & 31) == 0) sh[w] = v;
    __syncthreads();
    if (threadIdx.x < 8){
        v = sh[threadIdx.x];
        #pragma unroll
        for (int o = 4; o; o >>= 1) v += __shfl_xor_sync(0xffu, v, o);
        if (threadIdx.x == 0) sh[0] = v;
    }
    __syncthreads();
    v = sh[0];
    __syncthreads();
    return v;
}

// ---- addressing weights ----
__global__ void k_weights(int hibase, const float* __restrict__ prevw){
    int b = blockIdx.x;
    int hi = hibase + blockIdx.y;
    int slot = blockIdx.y;
    __shared__ float swg[N];
    __shared__ float sred[8];
    const float* dp = g_dot + (size_t)slot*BN_ + (size_t)b*N;
    const float* np = g_nrm + (size_t)b*N;
    const float* pw = prevw + (size_t)hi*BN_ + (size_t)b*N;
    float beta = g_beta[hi*B+b], gate = g_gate[hi*B+b];
    float kn = g_knorm[hi*B+b],  gam  = g_gamma[hi*B+b];
    float s0 = g_sv[(hi*B+b)*3+0], s1 = g_sv[(hi*B+b)*3+1], s2 = g_sv[(hi*B+b)*3+2];

    float sc[16];
    float mx = -1e30f;
    #pragma unroll
    for (int t = 0; t < 16; t++){
        int i = threadIdx.x + t*256;
        float v = beta * dp[i] / (np[i]*kn + EPS);
        sc[t] = v; mx = fmaxf(mx, v);
    }
    mx = blk_max_(mx, sred);
    float ls = 0.f;
    #pragma unroll
    for (int t = 0; t < 16; t++){ sc[t] = __expf(sc[t]-mx); ls += sc[t]; }
    float tot = blk_sum_(ls, sred);
    float inv = 1.f / tot;
    #pragma unroll
    for (int t = 0; t < 16; t++){
        int i = threadIdx.x + t*256;
        swg[i] = gate*sc[t]*inv + (1.f-gate)*pw[i];
    }
    __syncthreads();
    float lp[16]; float ls2 = 0.f;
    #pragma unroll
    for (int t = 0; t < 16; t++){
        int i = threadIdx.x + t*256;
        float ws = s0*swg[(i+N-1)&(N-1)] + s1*swg[i] + s2*swg[(i+1)&(N-1)];
        float wp = __powf(ws, gam);
        lp[t] = wp; ls2 += wp;
    }
    float tot2 = blk_sum_(ls2, sred);
    float inv2 = 1.f / (tot2 + EPS);
    #pragma unroll
    for (int t = 0; t < 16; t++){
        int i = threadIdx.x + t*256;
        g_w[(size_t)hi*BN_ + (size_t)b*N + i] = lp[t]*inv2;
    }
}

// ---- PASS 0: read fp32 memory (streaming); write fp16 image; dots + norms ----
__global__ void k_pass0(const float* __restrict__ mem){
    const int b   = blockIdx.y;
    const int n0  = blockIdx.x * 256;
    const int tid = threadIdx.x;
    const int lane = tid & 15, rg = tid >> 4;   // 16 rows/step

    __shared__ float4 skA[16], skB[16];
    if (tid < 16){
        skA[tid] = ((const float4*)(g_k + (size_t)0*B*M + b*M))[tid];
        skB[tid] = ((const float4*)(g_k + (size_t)1*B*M + b*M))[tid];
    }
    __syncthreads();
    const float4 kA = skA[lane], kB = skB[lane];

    const float4* mrow = (const float4*)mem + (size_t)b*N*(M/4);
    uint2* orow = (uint2*)g_mem16 + ((size_t)b*N)*(M/4);

    #pragma unroll
    for (int bt = 0; bt < 4; ++bt){
        float4 mv[4]; int ln[4];
        #pragma unroll
        for (int t = 0; t < 4; t++){
            ln[t] = n0 + bt*64 + t*16 + rg;
            mv[t] = __ldcs(&mrow[(size_t)ln[t]*(M/4) + lane]);
        }
        #pragma unroll
        for (int t = 0; t < 4; t++){
            float4 m = mv[t];
            __half2 ha = __floats2half2_rn(m.x, m.y);
            __half2 hb = __floats2half2_rn(m.z, m.w);
            uint2 st;
            st.x = *reinterpret_cast<const unsigned*>(&ha);
            st.y = *reinterpret_cast<const unsigned*>(&hb);
            orow[(size_t)ln[t]*(M/4) + lane] = st;

            size_t wi = (size_t)b*N + ln[t];
            float dA = m.x*kA.x + m.y*kA.y + m.z*kA.z + m.w*kA.w;
            float dB = m.x*kB.x + m.y*kB.y + m.z*kB.z + m.w*kB.w;
            float ss = m.x*m.x + m.y*m.y + m.z*m.z + m.w*m.w;
            #pragma unroll
            for (int o = 1; o < 16; o <<= 1){
                dA += __shfl_xor_sync(0xffffffffu, dA, o);
                dB += __shfl_xor_sync(0xffffffffu, dB, o);
                ss += __shfl_xor_sync(0xffffffffu, ss, o);
            }
            if (lane == 0){
                g_dot[wi]       = dA;
                g_dot[BN_ + wi] = dB;
                g_nrm[wi]       = sqrtf(ss);
            }
        }
    }
}

// ---- PASSES 1..4: fp16 image; w-arrays staged in smem (no LDG storm) ----
template<int PASS, bool REV>
__global__ void k_pass16(){
    constexpr int NPRE  = PASS - 1;
    constexpr int NPOST = (PASS <= 3) ? 1 : 0;
    constexpr int NAPP  = NPRE + NPOST;
    constexpr int NDOT  = (PASS == 4) ? 0 : ((PASS == 3) ? 1 : 2);
    constexpr int RSLOT = NPRE;
    constexpr int NARR  = NPRE + 1 + NPOST;     // w arrays consumed (<=4)
    constexpr int KB    = 2*PASS;

    const int bx = REV ? (int)(gridDim.x - 1 - blockIdx.x) : (int)blockIdx.x;
    const int b  = REV ? (int)(gridDim.y - 1 - blockIdx.y) : (int)blockIdx.y;
    const int n0 = bx * 256;
    const int tid = threadIdx.x;
    const int lane = tid & 15, rg = tid >> 4;   // 16 rows/step, 4 half-elems/lane

    __shared__ float sk[2][64], se[3][64], sa[3][64];
    __shared__ float sw[4][256];
    if (tid < 64){
        if (NDOT >= 1) sk[0][tid] = g_k[(size_t)(KB  )*B*M + b*M + tid];
        if (NDOT >= 2) sk[1][tid] = g_k[(size_t)(KB+1)*B*M + b*M + tid];
        #pragma unroll
        for (int j = 0; j < NAPP; j++){
            se[j][tid] = g_e[(size_t)j*B*M + b*M + tid];
            sa[j][tid] = g_a[(size_t)j*B*M + b*M + tid];
        }
    }
    // cooperative stage of w arrays: one coalesced load per array
    #pragma unroll
    for (int ar = 0; ar < NARR; ar++){
        int slot = (ar < NPRE) ? (2*ar+1) : ((ar == NPRE) ? 2*NPRE : 2*NPRE+1);
        sw[ar][tid] = g_w[(size_t)slot*BN_ + (size_t)b*N + n0 + tid];
    }
    __syncthreads();

    float kr0[4], kr1[4], er[3][4], ar_[3][4];
    #pragma unroll
    for (int t = 0; t < 4; t++){
        int ix = lane*4 + t;
        if (NDOT >= 1) kr0[t] = sk[0][ix];
        if (NDOT >= 2) kr1[t] = sk[1][ix];
        #pragma unroll
        for (int j = 0; j < NAPP; j++){ er[j][t] = se[j][ix]; ar_[j][t] = sa[j][ix]; }
    }

    const uint2* base = (const uint2*)g_mem16 + ((size_t)b*N + n0)*(M/4);
    float racc[4] = {0.f, 0.f, 0.f, 0.f};

    #pragma unroll
    for (int bt = 0; bt < 4; ++bt){
        uint2 raw[4]; int ln[4];
        float wv[4][4];   // [arr][row]
        #pragma unroll
        for (int t = 0; t < 4; t++){
            ln[t] = bt*64 + t*16 + rg;
            raw[t] = base[(size_t)ln[t]*(M/4) + lane];
        }
        // prefetch w scalars from smem while LDGs are in flight (broadcast LDS)
        #pragma unroll
        for (int arr = 0; arr < NARR; arr++)
            #pragma unroll
            for (int t = 0; t < 4; t++)
                wv[arr][t] = sw[arr][ln[t]];

        #pragma unroll
        for (int t = 0; t < 4; t++){
            float f[4];
            {
                __half2 h0 = *reinterpret_cast<const __half2*>(&raw[t].x);
                __half2 h1 = *reinterpret_cast<const __half2*>(&raw[t].y);
                float2 a0 = __half22float2(h0), a1 = __half22float2(h1);
                f[0]=a0.x; f[1]=a0.y; f[2]=a1.x; f[3]=a1.y;
            }
            #pragma unroll
            for (int j = 0; j < NPRE; j++){
                float w_ = wv[j][t];
                #pragma unroll
                for (int q = 0; q < 4; q++)
                    f[q] = fmaf(w_, fmaf(-f[q], er[j][q], ar_[j][q]), f[q]);
            }
            {
                float w_ = wv[NPRE][t];
                #pragma unroll
                for (int q = 0; q < 4; q++) racc[q] = fmaf(w_, f[q], racc[q]);
            }
            if (NPOST){
                float w_ = wv[NPRE+1][t];
                #pragma unroll
                for (int q = 0; q < 4; q++)
                    f[q] = fmaf(w_, fmaf(-f[q], er[NPRE][q], ar_[NPRE][q]), f[q]);
            }
            if (NDOT >= 1){
                float dA = 0.f, dB = 0.f, ss = 0.f;
                #pragma unroll
                for (int q = 0; q < 4; q++){
                    dA = fmaf(f[q], kr0[q], dA);
                    if (NDOT >= 2) dB = fmaf(f[q], kr1[q], dB);
                    ss = fmaf(f[q], f[q], ss);
                }
                #pragma unroll
                for (int o = 1; o < 16; o <<= 1){
                    dA += __shfl_xor_sync(0xffffffffu, dA, o);
                    ss += __shfl_xor_sync(0xffffffffu, ss, o);
                    if (NDOT >= 2) dB += __shfl_xor_sync(0xffffffffu, dB, o);
                }
                if (lane == 0){
                    size_t wi = (size_t)b*N + n0 + ln[t];
                    g_dot[wi] = dA;
                    if (NDOT >= 2) g_dot[BN_ + wi] = dB;
                    g_nrm[wi] = sqrtf(ss);
                }
            }
        }
    }
    // block-level read reduction
    __shared__ float sr[16][64];
    #pragma unroll
    for (int q = 0; q < 4; q++) sr[rg][lane*4+q] = racc[q];
    __syncthreads();
    if (tid < 64){
        float s = 0.f;
        #pragma unroll
        for (int r = 0; r < 16; r++) s += sr[r][tid];
        atomicAdd(&g_reads[(size_t)RSLOT*B*M + b*M + tid], s);
    }
}

extern "C" void kernel_launch(void* const* d_in, const int* in_sizes, int n_in,
                              void* d_out, int out_size){
    const float* in_data = (const float*)d_in[0];
    const float* memory  = (const float*)d_in[1];
    const float* h0      = (const float*)d_in[2];
    const float* c0      = (const float*)d_in[3];
    const float* prevw   = (const float*)d_in[4];
    const float* prevr   = (const float*)d_in[5];
    const float* W_ih    = (const float*)d_in[6];
    const float* b_ih    = (const float*)d_in[7];
    const float* W_hh    = (const float*)d_in[8];
    const float* b_hh    = (const float*)d_in[9];
    const float* W_out   = (const float*)d_in[10];
    const float* b_out   = (const float*)d_in[11];
    const float* W_addr  = (const float*)d_in[12];
    const float* b_addr  = (const float*)d_in[13];
    const float* W_ea    = (const float*)d_in[14];
    const float* b_ea    = (const float*)d_in[15];
    float* out = (float*)d_out;

    // controller
    int prep_total = B*KL + 4*C*KL;
    k_prep<<<(prep_total + 255)/256, 256>>>(in_data, prevr, h0, W_ih, W_hh, b_ih, b_hh);
    k_gates<<<dim3(4*C/32, B/64), 256>>>(c0);
    k_proj<<<dim3((NPROJ+31)/32, B/64), 256>>>(W_addr, b_addr, W_ea, b_ea);
    k_head_params<<<dim3(B, 8), 64>>>();

    // memory passes (serpentine traversal for L2 reuse)
    dim3 pg(N/256, B);
    k_pass0<<<pg, 256>>>(memory);
    k_weights<<<dim3(B,2), 256>>>(0, prevw);
    k_pass16<1, true ><<<pg, 256>>>();
    k_weights<<<dim3(B,2), 256>>>(2, prevw);
    k_pass16<2, false><<<pg, 256>>>();
    k_weights<<<dim3(B,2), 256>>>(4, prevw);
    k_pass16<3, true ><<<pg, 256>>>();
    k_weights<<<dim3(B,1), 256>>>(6, prevw);
    k_pass16<4, false><<<pg, 256>>>();

    // output
    k_out<<<B, 256>>>(W_out, b_out, out);
}

// round 12
// speedup vs baseline: 1.6657x; 1.0278x over previous
#include <cuda_runtime.h>
#include <cuda_fp16.h>
#include <math.h>

// ---- problem constants ----
constexpr int B   = 256;
constexpr int N   = 4096;
constexpr int M   = 64;
constexpr int C   = 512;
constexpr int H   = 4;
constexpr int INP = 64;
constexpr int OUTD= 64;
constexpr int XPART = INP + H*M;      // 320
constexpr int KL    = XPART + C;      // 832
constexpr int NADDR = 2*H*(M+6);      // 560
constexpr int NEA   = H*2*M;          // 512
constexpr int NPROJ = NADDR + NEA;    // 1072
constexpr int KOUT  = C + H*M;        // 768
constexpr int BN_   = B*N;            // 1048576
constexpr float EPS = 1e-8f;

// ---- scratch (device globals: allocation-free) ----
__device__ float  g_xcat [B*KL];
__device__ float  g_Wcat [4*C*KL];    // interleaved rows: 4*ci + gate
__device__ float  g_bcat [4*C];
__device__ float  g_hst  [B*C];
__device__ float  g_cst  [B*C];
__device__ float  g_P    [B*NPROJ];
__device__ float  g_k    [8*B*M];
__device__ float  g_knorm[8*B];
__device__ float  g_beta [8*B];
__device__ float  g_gate [8*B];
__device__ float  g_sv   [8*B*3];
__device__ float  g_gamma[8*B];
__device__ float  g_e    [4*B*M];
__device__ float  g_a    [4*B*M];
__device__ float  g_w    [7*BN_];
__device__ float  g_dot  [2*BN_];
__device__ float  g_nrm  [BN_];
__device__ float  g_reads[4*B*M];
__device__ __half g_mem16[(size_t)B*N*M];

__device__ __forceinline__ float sigmoidf_(float x){ return 1.f/(1.f+__expf(-x)); }
__device__ __forceinline__ float softplusf_(float x){ return x>20.f ? x : log1pf(__expf(x)); }

// ---- packed f32x2 helpers (Blackwell FFMA2) ----
typedef unsigned long long u64_;
__device__ __forceinline__ u64_ pk2(float lo, float hi){
    u64_ d; asm("mov.b64 %0, {%1,%2};" : "=l"(d) : "f"(lo), "f"(hi)); return d;
}
__device__ __forceinline__ void upk2(u64_ d, float& lo, float& hi){
    asm("mov.b64 {%0,%1}, %2;" : "=f"(lo), "=f"(hi) : "l"(d));
}
__device__ __forceinline__ u64_ ffma2_(u64_ a, u64_ b, u64_ c){
    u64_ d; asm("fma.rn.f32x2 %0, %1, %2, %3;" : "=l"(d) : "l"(a), "l"(b), "l"(c)); return d;
}

__device__ __forceinline__ void cp_async4(void* sdst, const void* gsrc){
    unsigned s = (unsigned)__cvta_generic_to_shared(sdst);
    asm volatile("cp.async.ca.shared.global [%0], [%1], 4;" :: "r"(s), "l"(gsrc));
}
__device__ __forceinline__ void cp_commit(){ asm volatile("cp.async.commit_group;"); }
template<int NG> __device__ __forceinline__ void cp_wait(){ asm volatile("cp.async.wait_group %0;" :: "n"(NG)); }

// ---- fused builder: xcat + interleaved Wcat + bcat ----
__global__ void k_prep(const float* __restrict__ ind, const float* __restrict__ prd,
                       const float* __restrict__ h0,
                       const float* __restrict__ W_ih, const float* __restrict__ W_hh,
                       const float* __restrict__ b_ih, const float* __restrict__ b_hh){
    int idx = blockIdx.x*blockDim.x + threadIdx.x;
    if (idx < B*KL){
        int b = idx / KL, j = idx % KL;
        float v;
        if (j < INP)            v = ind[b*INP + j];
        else if (j < XPART) {   int r = j - INP; v = prd[(r/M)*B*M + b*M + (r%M)]; }
        else                    v = h0[b*C + (j - XPART)];
        g_xcat[idx] = v;
    }
    int idx2 = idx - B*KL;
    if (idx2 >= 0 && idx2 < 4*C*KL){
        int j = idx2 / KL, kk = idx2 % KL;
        int ci = j >> 2, gg = j & 3;
        int src = gg*C + ci;
        g_Wcat[idx2] = (kk < XPART) ? W_ih[(size_t)src*XPART + kk] : W_hh[(size_t)src*C + (kk - XPART)];
        if (kk == 0) g_bcat[j] = b_ih[src] + b_hh[src];
    }
}

// ============ pipelined GEMM: gates + fused LSTM epilogue ============
__global__ void k_gates(const float* __restrict__ c0){
    constexpr int K = KL, NK = K/16;
    __shared__ float As[2][64][17];
    __shared__ float Ws[2][32][17];
    const int tid = threadIdx.x;
    const int tx = tid & 7, ty = tid >> 3;
    const int bn = blockIdx.x*32, bm = blockIdx.y*64;
    const float* A = g_xcat;
    const float* W = g_Wcat;

    auto prefetch = [&](int kb, int buf){
        int k0 = kb*16;
        #pragma unroll
        for (int r = 0; r < 4; r++){
            int idx = tid + r*256;
            int i = idx >> 4, k = idx & 15;
            cp_async4(&As[buf][i][k], &A[(size_t)(bm+i)*K + k0 + k]);
        }
        #pragma unroll
        for (int r = 0; r < 2; r++){
            int idx = tid + r*256;
            int i = idx >> 4, k = idx & 15;
            cp_async4(&Ws[buf][i][k], &W[(size_t)(bn+i)*K + k0 + k]);
        }
    };

    float acc[2][4] = {};
    prefetch(0, 0); cp_commit();
    for (int kb = 0; kb < NK; kb++){
        int cur = kb & 1;
        if (kb+1 < NK){ prefetch(kb+1, cur^1); cp_commit(); cp_wait<1>(); }
        else cp_wait<0>();
        __syncthreads();
        #pragma unroll
        for (int k = 0; k < 16; k++){
            float av0 = As[cur][ty*2+0][k], av1 = As[cur][ty*2+1][k];
            float wv[4];
            #pragma unroll
            for (int j = 0; j < 4; j++) wv[j] = Ws[cur][tx*4+j][k];
            #pragma unroll
            for (int j = 0; j < 4; j++){ acc[0][j] += av0*wv[j]; acc[1][j] += av1*wv[j]; }
        }
        __syncthreads();
    }
    int ci = (bn >> 2) + tx;
    #pragma unroll
    for (int i = 0; i < 2; i++){
        int m = bm + ty*2 + i;
        float ig = acc[i][0] + g_bcat[bn + tx*4 + 0];
        float fg = acc[i][1] + g_bcat[bn + tx*4 + 1];
        float gg = acc[i][2] + g_bcat[bn + tx*4 + 2];
        float og = acc[i][3] + g_bcat[bn + tx*4 + 3];
        float cn = sigmoidf_(fg)*c0[(size_t)m*C + ci] + sigmoidf_(ig)*tanhf(gg);
        g_cst[(size_t)m*C + ci] = cn;
        g_hst[(size_t)m*C + ci] = sigmoidf_(og)*tanhf(cn);
    }
}

// ============ pipelined GEMM: fused addr+ea projections ============
__global__ void k_proj(const float* __restrict__ W1, const float* __restrict__ b1,
                       const float* __restrict__ W2, const float* __restrict__ b2){
    constexpr int K = C, NK = K/16, No = NPROJ;
    __shared__ float As[2][64][17];
    __shared__ float Ws[2][32][17];
    const int tid = threadIdx.x;
    const int tx = tid & 7, ty = tid >> 3;
    const int bn = blockIdx.x*32, bm = blockIdx.y*64;
    const float* A = g_cst;

    auto prefetch = [&](int kb, int buf){
        int k0 = kb*16;
        #pragma unroll
        for (int r = 0; r < 4; r++){
            int idx = tid + r*256;
            int i = idx >> 4, k = idx & 15;
            cp_async4(&As[buf][i][k], &A[(size_t)(bm+i)*K + k0 + k]);
        }
        #pragma unroll
        for (int r = 0; r < 2; r++){
            int idx = tid + r*256;
            int i = idx >> 4, k = idx & 15;
            int j = bn + i; if (j > No-1) j = No-1;
            const float* src = (j < NADDR) ? &W1[(size_t)j*K + k0 + k]
                                           : &W2[(size_t)(j-NADDR)*K + k0 + k];
            cp_async4(&Ws[buf][i][k], src);
        }
    };

    float acc[2][4] = {};
    prefetch(0, 0); cp_commit();
    for (int kb = 0; kb < NK; kb++){
        int cur = kb & 1;
        if (kb+1 < NK){ prefetch(kb+1, cur^1); cp_commit(); cp_wait<1>(); }
        else cp_wait<0>();
        __syncthreads();
        #pragma unroll
        for (int k = 0; k < 16; k++){
            float av0 = As[cur][ty*2+0][k], av1 = As[cur][ty*2+1][k];
            float wv[4];
            #pragma unroll
            for (int j = 0; j < 4; j++) wv[j] = Ws[cur][tx*4+j][k];
            #pragma unroll
            for (int j = 0; j < 4; j++){ acc[0][j] += av0*wv[j]; acc[1][j] += av1*wv[j]; }
        }
        __syncthreads();
    }
    #pragma unroll
    for (int i = 0; i < 2; i++){
        int m = bm + ty*2 + i;
        #pragma unroll
        for (int j = 0; j < 4; j++){
            int n = bn + tx*4 + j;
            if (n < No){
                float bb = (n < NADDR) ? b1[n] : b2[n - NADDR];
                g_P[(size_t)m*No + n] = acc[i][j] + bb;
            }
        }
    }
}

// ============ output layer ============
__global__ void k_out(const float* __restrict__ W, const float* __restrict__ bias,
                      float* __restrict__ out){
    const int m = blockIdx.x;
    const int tid = threadIdx.x, lane = tid & 31, wid = tid >> 5;
    __shared__ float sA[KOUT];
    for (int idx = tid; idx < KOUT; idx += 256){
        float v;
        if (idx < C) v = g_hst[(size_t)m*C + idx];
        else { int r = idx - C; v = g_reads[(size_t)(r>>6)*B*M + m*M + (r&63)]; }
        sA[idx] = v;
    }
    __syncthreads();
    #pragma unroll
    for (int nn = 0; nn < 8; nn++){
        int n = wid*8 + nn;
        const float* wr = &W[(size_t)n*KOUT];
        float s = 0.f;
        #pragma unroll 6
        for (int kk = lane; kk < KOUT; kk += 32) s += sA[kk]*wr[kk];
        #pragma unroll
        for (int o = 16; o; o >>= 1) s += __shfl_xor_sync(0xffffffffu, s, o);
        if (lane == 0) out[(size_t)m*OUTD + n] = sigmoidf_(s + bias[n]);
    }
}

// ---- per-head addressing params ----
__global__ void k_head_params(){
    int b = blockIdx.x, hi = blockIdx.y, t = threadIdx.x;
    const float* pa = g_P + (size_t)b*NPROJ + hi*70;
    float kv = tanhf(pa[t]);
    g_k[(size_t)(hi*B + b)*M + t] = kv;
    float sq = kv*kv;
    #pragma unroll
    for (int o = 16; o; o >>= 1) sq += __shfl_xor_sync(0xffffffffu, sq, o);
    __shared__ float sh[2];
    if ((t & 31) == 0) sh[t >> 5] = sq;
    __syncthreads();
    if (t == 0){
        g_knorm[hi*B + b] = sqrtf(sh[0] + sh[1]);
        g_beta [hi*B + b] = softplusf_(pa[64]);
        g_gate [hi*B + b] = sigmoidf_(pa[65]);
        float p0 = pa[66], p1 = pa[67], p2 = pa[68];
        float mx = fmaxf(p0, fmaxf(p1, p2));
        float e0 = __expf(p0-mx), e1 = __expf(p1-mx), e2 = __expf(p2-mx);
        float ssum = e0 + e1 + e2;
        g_sv[(hi*B+b)*3+0] = e0/ssum;
        g_sv[(hi*B+b)*3+1] = e1/ssum;
        g_sv[(hi*B+b)*3+2] = e2/ssum;
        g_gamma[hi*B + b] = 1.f + softplusf_(pa[69]);
    }
    if (hi & 1){
        int j = hi >> 1;
        const float* pe = g_P + (size_t)b*NPROJ + NADDR + j*128;
        g_e[(size_t)j*B*M + b*M + t] = sigmoidf_(pe[t]);
        g_a[(size_t)j*B*M + b*M + t] = tanhf(pe[64+t]);
    }
    if (hi < 4) g_reads[(size_t)hi*B*M + b*M + t] = 0.f;
}

// ---- block reduction helpers (256 threads) ----
__device__ __forceinline__ float blk_max_(float v, float* sh){
    #pragma unroll
    for (int o = 16; o; o >>= 1) v = fmaxf(v, __shfl_xor_sync(0xffffffffu, v, o));
    int w = threadIdx.x >> 5;
    if ((threadIdx.x & 31) == 0) sh[w] = v;
    __syncthreads();
    if (threadIdx.x < 8){
        v = sh[threadIdx.x];
        #pragma unroll
        for (int o = 4; o; o >>= 1) v = fmaxf(v, __shfl_xor_sync(0xffu, v, o));
        if (threadIdx.x == 0) sh[0] = v;
    }
    __syncthreads();
    v = sh[0];
    __syncthreads();
    return v;
}
__device__ __forceinline__ float blk_sum_(float v, float* sh){
    #pragma unroll
    for (int o = 16; o; o >>= 1) v += __shfl_xor_sync(0xffffffffu, v, o);
    int w = threadIdx.x >> 5;
    if ((threadIdx.x & 31) == 0) sh[w] = v;
    __syncthreads();
    if (threadIdx.x < 8){
        v = sh[threadIdx.x];
        #pragma unroll
        for (int o = 4; o; o >>= 1) v += __shfl_xor_sync(0xffu, v, o);
        if (threadIdx.x == 0) sh[0] = v;
    }
    __syncthreads();
    v = sh[0];
    __syncthreads();
    return v;
}

// ---- addressing weights ----
__global__ void k_weights(int hibase, const float* __restrict__ prevw){
    int b = blockIdx.x;
    int hi = hibase + blockIdx.y;
    int slot = blockIdx.y;
    __shared__ float swg[N];
    __shared__ float sred[8];
    const float* dp = g_dot + (size_t)slot*BN_ + (size_t)b*N;
    const float* np = g_nrm + (size_t)b*N;
    const float* pw = prevw + (size_t)hi*BN_ + (size_t)b*N;
    float beta = g_beta[hi*B+b], gate = g_gate[hi*B+b];
    float kn = g_knorm[hi*B+b],  gam  = g_gamma[hi*B+b];
    float s0 = g_sv[(hi*B+b)*3+0], s1 = g_sv[(hi*B+b)*3+1], s2 = g_sv[(hi*B+b)*3+2];

    float sc[16];
    float mx = -1e30f;
    #pragma unroll
    for (int t = 0; t < 16; t++){
        int i = threadIdx.x + t*256;
        float v = beta * dp[i] / (np[i]*kn + EPS);
        sc[t] = v; mx = fmaxf(mx, v);
    }
    mx = blk_max_(mx, sred);
    float ls = 0.f;
    #pragma unroll
    for (int t = 0; t < 16; t++){ sc[t] = __expf(sc[t]-mx); ls += sc[t]; }
    float tot = blk_sum_(ls, sred);
    float inv = 1.f / tot;
    #pragma unroll
    for (int t = 0; t < 16; t++){
        int i = threadIdx.x + t*256;
        swg[i] = gate*sc[t]*inv + (1.f-gate)*pw[i];
    }
    __syncthreads();
    float lp[16]; float ls2 = 0.f;
    #pragma unroll
    for (int t = 0; t < 16; t++){
        int i = threadIdx.x + t*256;
        float ws = s0*swg[(i+N-1)&(N-1)] + s1*swg[i] + s2*swg[(i+1)&(N-1)];
        float wp = __powf(ws, gam);
        lp[t] = wp; ls2 += wp;
    }
    float tot2 = blk_sum_(ls2, sred);
    float inv2 = 1.f / (tot2 + EPS);
    #pragma unroll
    for (int t = 0; t < 16; t++){
        int i = threadIdx.x + t*256;
        g_w[(size_t)hi*BN_ + (size_t)b*N + i] = lp[t]*inv2;
    }
}

// ---- PASS 0: fp32 memory (streaming) -> fp16 image; dots(k0,k1)+norms; f32x2 math ----
// 8 lanes/row, 8 floats/lane (2x float4), MLP=4
__global__ void __launch_bounds__(256) k_pass0(const float* __restrict__ mem){
    const int b   = blockIdx.y;
    const int n0  = blockIdx.x * 256;
    const int tid = threadIdx.x;
    const int lane = tid & 7, rg = tid >> 3;   // 32 rows/step

    __shared__ float sk[2][64];
    if (tid < 64){
        sk[0][tid] = g_k[(size_t)0*B*M + b*M + tid];
        sk[1][tid] = g_k[(size_t)1*B*M + b*M + tid];
    }
    __syncthreads();
    const int ix = lane*8;
    u64_ kA2[4], kB2[4];
    #pragma unroll
    for (int q = 0; q < 4; q++){
        kA2[q] = pk2(sk[0][ix+2*q], sk[0][ix+2*q+1]);
        kB2[q] = pk2(sk[1][ix+2*q], sk[1][ix+2*q+1]);
    }

    const float4* mrow = (const float4*)mem + ((size_t)b*N + n0)*(M/4);
    uint4* orow = (uint4*)g_mem16 + ((size_t)b*N + n0)*(M/8);

    #pragma unroll
    for (int bt = 0; bt < 2; ++bt){
        float4 fa[4], fb[4]; int ln[4];
        #pragma unroll
        for (int t = 0; t < 4; t++){
            ln[t] = bt*128 + t*32 + rg;
            fa[t] = __ldcs(&mrow[(size_t)ln[t]*16 + lane*2 + 0]);
            fb[t] = __ldcs(&mrow[(size_t)ln[t]*16 + lane*2 + 1]);
        }
        #pragma unroll
        for (int t = 0; t < 4; t++){
            // fp16 store (one STG.128)
            __half2 h0 = __floats2half2_rn(fa[t].x, fa[t].y);
            __half2 h1 = __floats2half2_rn(fa[t].z, fa[t].w);
            __half2 h2 = __floats2half2_rn(fb[t].x, fb[t].y);
            __half2 h3 = __floats2half2_rn(fb[t].z, fb[t].w);
            uint4 st;
            st.x = *reinterpret_cast<const unsigned*>(&h0);
            st.y = *reinterpret_cast<const unsigned*>(&h1);
            st.z = *reinterpret_cast<const unsigned*>(&h2);
            st.w = *reinterpret_cast<const unsigned*>(&h3);
            orow[(size_t)ln[t]*8 + lane] = st;

            u64_ p[4];
            p[0] = pk2(fa[t].x, fa[t].y); p[1] = pk2(fa[t].z, fa[t].w);
            p[2] = pk2(fb[t].x, fb[t].y); p[3] = pk2(fb[t].z, fb[t].w);
            u64_ dA2 = 0ull, dB2 = 0ull, ss2 = 0ull;
            #pragma unroll
            for (int q = 0; q < 4; q++){
                dA2 = ffma2_(p[q], kA2[q], dA2);
                dB2 = ffma2_(p[q], kB2[q], dB2);
                ss2 = ffma2_(p[q], p[q], ss2);
            }
            float lo, hi2, dA, dB, ss;
            upk2(dA2, lo, hi2); dA = lo + hi2;
            upk2(dB2, lo, hi2); dB = lo + hi2;
            upk2(ss2, lo, hi2); ss = lo + hi2;
            #pragma unroll
            for (int o = 1; o < 8; o <<= 1){
                dA += __shfl_xor_sync(0xffffffffu, dA, o);
                dB += __shfl_xor_sync(0xffffffffu, dB, o);
                ss += __shfl_xor_sync(0xffffffffu, ss, o);
            }
            if (lane == 0){
                size_t wi = (size_t)b*N + n0 + ln[t];
                g_dot[wi]       = dA;
                g_dot[BN_ + wi] = dB;
                g_nrm[wi]       = sqrtf(ss);
            }
        }
    }
}

// ---- PASSES 1..4: fp16 image; half2 pre-chain + f32x2 read/post/dots ----
// 8 lanes/row, 8 elems/lane (uint4), MLP=4, serpentine
template<int PASS, bool REV>
__global__ void __launch_bounds__(256) k_pass16(){
    constexpr int NPRE  = PASS - 1;
    constexpr int NPOST = (PASS <= 3) ? 1 : 0;
    constexpr int NDOT  = (PASS == 4) ? 0 : ((PASS == 3) ? 1 : 2);
    constexpr int RSLOT = NPRE;
    constexpr int NARR  = NPRE + 1 + NPOST;
    constexpr int KB    = 2*PASS;

    const int bx = REV ? (int)(gridDim.x - 1 - blockIdx.x) : (int)blockIdx.x;
    const int b  = REV ? (int)(gridDim.y - 1 - blockIdx.y) : (int)blockIdx.y;
    const int n0 = bx * 256;
    const int tid = threadIdx.x;
    const int lane = tid & 7, rg = tid >> 3;   // 32 rows/step

    __shared__ float sk[2][64], se[3][64], sa[3][64];
    __shared__ float sw[4][256];
    if (tid < 64){
        if (NDOT >= 1) sk[0][tid] = g_k[(size_t)(KB  )*B*M + b*M + tid];
        if (NDOT >= 2) sk[1][tid] = g_k[(size_t)(KB+1)*B*M + b*M + tid];
        #pragma unroll
        for (int j = 0; j < NPRE + NPOST; j++){
            se[j][tid] = g_e[(size_t)j*B*M + b*M + tid];
            sa[j][tid] = g_a[(size_t)j*B*M + b*M + tid];
        }
    }
    #pragma unroll
    for (int ar = 0; ar < NARR; ar++){
        int slot = (ar < NPRE) ? (2*ar+1) : ((ar == NPRE) ? 2*NPRE : 2*NPRE+1);
        sw[ar][tid] = g_w[(size_t)slot*BN_ + (size_t)b*N + n0 + tid];
    }
    __syncthreads();

    const int ix = lane*8;
    // pre-chain constants in half2 (e negated)
    __half2 eh[3][4], ah[3][4];
    #pragma unroll
    for (int j = 0; j < NPRE; j++)
        #pragma unroll
        for (int q = 0; q < 4; q++){
            eh[j][q] = __floats2half2_rn(-se[j][ix+2*q], -se[j][ix+2*q+1]);
            ah[j][q] = __floats2half2_rn( sa[j][ix+2*q],  sa[j][ix+2*q+1]);
        }
    // post-chain constants in f32x2 (e negated)
    u64_ ep2[4], ap2[4];
    if (NPOST)
        #pragma unroll
        for (int q = 0; q < 4; q++){
            ep2[q] = pk2(-se[NPRE][ix+2*q], -se[NPRE][ix+2*q+1]);
            ap2[q] = pk2( sa[NPRE][ix+2*q],  sa[NPRE][ix+2*q+1]);
        }
    // keys in f32x2
    u64_ k02[4], k12[4];
    if (NDOT >= 1)
        #pragma unroll
        for (int q = 0; q < 4; q++) k02[q] = pk2(sk[0][ix+2*q], sk[0][ix+2*q+1]);
    if (NDOT >= 2)
        #pragma unroll
        for (int q = 0; q < 4; q++) k12[q] = pk2(sk[1][ix+2*q], sk[1][ix+2*q+1]);

    const uint4* base = (const uint4*)g_mem16 + ((size_t)b*N + n0)*(M/8);
    u64_ racc2[4] = {0ull, 0ull, 0ull, 0ull};

    #pragma unroll
    for (int bt = 0; bt < 2; ++bt){
        uint4 raw[4]; int ln[4];
        float wvv[4][4];
        #pragma unroll
        for (int t = 0; t < 4; t++){
            ln[t] = bt*128 + t*32 + rg;
            raw[t] = base[(size_t)ln[t]*8 + lane];
        }
        #pragma unroll
        for (int arr = 0; arr < NARR; arr++)
            #pragma unroll
            for (int t = 0; t < 4; t++)
                wvv[arr][t] = sw[arr][ln[t]];

        #pragma unroll
        for (int t = 0; t < 4; t++){
            __half2 f[4];
            f[0] = *reinterpret_cast<const __half2*>(&raw[t].x);
            f[1] = *reinterpret_cast<const __half2*>(&raw[t].y);
            f[2] = *reinterpret_cast<const __half2*>(&raw[t].z);
            f[3] = *reinterpret_cast<const __half2*>(&raw[t].w);
            // pre-chain in half2:  f += w*(a - f*e)
            #pragma unroll
            for (int j = 0; j < NPRE; j++){
                __half2 w2 = __float2half2_rn(wvv[j][t]);
                #pragma unroll
                for (int q = 0; q < 4; q++)
                    f[q] = __hfma2(w2, __hfma2(f[q], eh[j][q], ah[j][q]), f[q]);
            }
            // convert once to f32x2
            u64_ fp[4];
            #pragma unroll
            for (int q = 0; q < 4; q++){
                float2 v = __half22float2(f[q]);
                fp[q] = pk2(v.x, v.y);
            }
            // read accumulate (f32x2)
            {
                float wr = wvv[NPRE][t];
                u64_ wr2 = pk2(wr, wr);
                #pragma unroll
                for (int q = 0; q < 4; q++) racc2[q] = ffma2_(wr2, fp[q], racc2[q]);
            }
            // post-chain (f32x2)
            if (NPOST){
                float wp = wvv[NPRE+1][t];
                u64_ wp2 = pk2(wp, wp);
                #pragma unroll
                for (int q = 0; q < 4; q++)
                    fp[q] = ffma2_(wp2, ffma2_(fp[q], ep2[q], ap2[q]), fp[q]);
            }
            // dots (f32x2) + 3-stage shuffle over 8 lanes
            if (NDOT >= 1){
                u64_ dA2 = 0ull, dB2 = 0ull, ss2 = 0ull;
                #pragma unroll
                for (int q = 0; q < 4; q++){
                    dA2 = ffma2_(fp[q], k02[q], dA2);
                    if (NDOT >= 2) dB2 = ffma2_(fp[q], k12[q], dB2);
                    ss2 = ffma2_(fp[q], fp[q], ss2);
                }
                float lo, hi2;
                float dA, dB = 0.f, ss;
                upk2(dA2, lo, hi2); dA = lo + hi2;
                upk2(ss2, lo, hi2); ss = lo + hi2;
                if (NDOT >= 2){ upk2(dB2, lo, hi2); dB = lo + hi2; }
                #pragma unroll
                for (int o = 1; o < 8; o <<= 1){
                    dA += __shfl_xor_sync(0xffffffffu, dA, o);
                    ss += __shfl_xor_sync(0xffffffffu, ss, o);
                    if (NDOT >= 2) dB += __shfl_xor_sync(0xffffffffu, dB, o);
                }
                if (lane == 0){
                    size_t wi = (size_t)b*N + n0 + ln[t];
                    g_dot[wi] = dA;
                    if (NDOT >= 2) g_dot[BN_ + wi] = dB;
                    g_nrm[wi] = sqrtf(ss);
                }
            }
        }
    }
    // block-level read reduction
    __shared__ float sr[32][64];
    #pragma unroll
    for (int q = 0; q < 4; q++){
        float lo, hi2;
        upk2(racc2[q], lo, hi2);
        sr[rg][ix + 2*q]     = lo;
        sr[rg][ix + 2*q + 1] = hi2;
    }
    __syncthreads();
    if (tid < 64){
        float s = 0.f;
        #pragma unroll
        for (int r = 0; r < 32; r++) s += sr[r][tid];
        atomicAdd(&g_reads[(size_t)RSLOT*B*M + b*M + tid], s);
    }
}

extern "C" void kernel_launch(void* const* d_in, const int* in_sizes, int n_in,
                              void* d_out, int out_size){
    const float* in_data = (const float*)d_in[0];
    const float* memory  = (const float*)d_in[1];
    const float* h0      = (const float*)d_in[2];
    const float* c0      = (const float*)d_in[3];
    const float* prevw   = (const float*)d_in[4];
    const float* prevr   = (const float*)d_in[5];
    const float* W_ih    = (const float*)d_in[6];
    const float* b_ih    = (const float*)d_in[7];
    const float* W_hh    = (const float*)d_in[8];
    const float* b_hh    = (const float*)d_in[9];
    const float* W_out   = (const float*)d_in[10];
    const float* b_out   = (const float*)d_in[11];
    const float* W_addr  = (const float*)d_in[12];
    const float* b_addr  = (const float*)d_in[13];
    const float* W_ea    = (const float*)d_in[14];
    const float* b_ea    = (const float*)d_in[15];
    float* out = (float*)d_out;

    // controller
    int prep_total = B*KL + 4*C*KL;
    k_prep<<<(prep_total + 255)/256, 256>>>(in_data, prevr, h0, W_ih, W_hh, b_ih, b_hh);
    k_gates<<<dim3(4*C/32, B/64), 256>>>(c0);
    k_proj<<<dim3((NPROJ+31)/32, B/64), 256>>>(W_addr, b_addr, W_ea, b_ea);
    k_head_params<<<dim3(B, 8), 64>>>();

    // memory passes (serpentine traversal for L2 reuse)
    dim3 pg(N/256, B);
    k_pass0<<<pg, 256>>>(memory);
    k_weights<<<dim3(B,2), 256>>>(0, prevw);
    k_pass16<1, true ><<<pg, 256>>>();
    k_weights<<<dim3(B,2), 256>>>(2, prevw);
    k_pass16<2, false><<<pg, 256>>>();
    k_weights<<<dim3(B,2), 256>>>(4, prevw);
    k_pass16<3, true ><<<pg, 256>>>();
    k_weights<<<dim3(B,1), 256>>>(6, prevw);
    k_pass16<4, false><<<pg, 256>>>();

    // output
    k_out<<<B, 256>>>(W_out, b_out, out);
}